// round 14
// baseline (speedup 1.0000x reference)
#include <cuda_runtime.h>
#include <cuda_fp16.h>
#include <cstdint>
#include <math.h>

// Problem constants
#define B_DIM   1024
#define S_IN    4096
#define S_OUTD  4096
#define KNOT    8
#define HID     512
#define NCOL    (S_OUTD * 3 * KNOT)    // 98304
#define NELEM   ((size_t)B_DIM * S_IN) // 4194304
#define TWO_PI_F 6.28318530717958647692f
#define EPS_F    1e-6f
#define LO_SCALE 2048.0f
#define LO_INVF  (1.0f / 2048.0f)

// wsplit partition: 24576 blocks total, split across fuse1/fuse2
#define WS_TOTAL 24576
#define WS_F1    12288
#define WS_F2    (WS_TOTAL - WS_F1)    // 12288

// ---------------- device scratch (static, no allocation) ----------------
static __device__ double g_ps[256];
static __device__ double g_ps2[256];
static __device__ float  g_mean;
static __device__ float  g_std;
static __device__ int    g_flag[16];                                 // gemm1 m-tile done counters
static __device__ __align__(16) float g_part[(size_t)B_DIM * 1024];  // 4 MB
// fp16 2-way splits (lo pre-scaled by 2048)
static __device__ __align__(16) __half g_XNh[NELEM];                // xn
static __device__ __align__(16) __half g_XNl[NELEM];
static __device__ __align__(16) __half g_W1h[(size_t)HID * S_IN];   // w1^T
static __device__ __align__(16) __half g_W1l[(size_t)HID * S_IN];
static __device__ __align__(16) __half g_Ah[B_DIM * HID];           // H
static __device__ __align__(16) __half g_Al[B_DIM * HID];
static __device__ __align__(16) __half g_Bh[(size_t)NCOL * HID];    // w2^T
static __device__ __align__(16) __half g_Bl[(size_t)NCOL * HID];

// ---------------- FMA-pipe transcendentals (avoid MUFU) ------------------
static __device__ __forceinline__ float fexp(float x) {
    float t = x * 1.4426950408889634f;          // log2(e)
    float n = rintf(t);
    float f = fmaf(n, -0.693359375f, x);        // ln2 hi
    f = fmaf(n, 2.12194440e-4f, f);             // ln2 lo
    float p = 1.9841269841e-4f;
    p = fmaf(p, f, 1.3888888889e-3f);
    p = fmaf(p, f, 8.3333333333e-3f);
    p = fmaf(p, f, 4.1666666667e-2f);
    p = fmaf(p, f, 1.6666666667e-1f);
    p = fmaf(p, f, 0.5f);
    p = fmaf(p, f, 1.0f);
    p = fmaf(p, f, 1.0f);
    int j = (int)n;
    float s = __int_as_float((j + 127) << 23);
    return p * s;
}

static __device__ __forceinline__ float ftanh(float x) {
    float a = fminf(fabsf(x), 9.0f);
    float e = fexp(-2.0f * a);
    float d = 1.0f + e;
    float r;
    asm("rcp.approx.f32 %0, %1;" : "=f"(r) : "f"(d));
    r = r * (2.0f - d * r);
    float tt = (1.0f - e) * r;
    return copysignf(tt, x);
}

// ---------------- float-float (TwoSum) helpers ---------------------------
struct ff2 { float hi, lo; };
static __device__ __forceinline__ ff2 ff_renorm(float s, float e) {
    float t = s + e;
    return {t, e - (t - s)};
}
static __device__ __forceinline__ ff2 ff_addf(ff2 a, float b) {
    float s  = a.hi + b;
    float bb = s - a.hi;
    float err = (a.hi - (s - bb)) + (b - bb);
    return ff_renorm(s, err + a.lo);
}

// ---------------- wsplit body (shared by the fused kernels) -------------
static __device__ __forceinline__ void wsplit_body(const float* __restrict__ w2,
                                                   int wb, float* scratch) {
    const int n0 = (wb % 3072) * 32;
    const int k0 = (wb / 3072) * 64;
    const int tid = threadIdx.x;
#pragma unroll
    for (int p = 0; p < 8; p++) {
        int idx = tid + p * 256;
        int kr = idx >> 5, nc = idx & 31;
        scratch[kr * 33 + nc] = w2[(size_t)(k0 + kr) * NCOL + n0 + nc];
    }
    __syncthreads();
#pragma unroll
    for (int p = 0; p < 4; p++) {
        int idx = tid + p * 256;
        int n = idx >> 5, kp = idx & 31;
        float v0 = scratch[(2 * kp) * 33 + n];
        float v1 = scratch[(2 * kp + 1) * 33 + n];
        __half h0 = __float2half_rn(v0);
        __half h1 = __float2half_rn(v1);
        __half l0 = __float2half_rn((v0 - __half2float(h0)) * LO_SCALE);
        __half l1 = __float2half_rn((v1 - __half2float(h1)) * LO_SCALE);
        size_t o = ((size_t)(n0 + n) * HID + k0 + 2 * kp) >> 1;
        ((__half2*)g_Bh)[o] = __halves2half2(h0, h1);
        ((__half2*)g_Bl)[o] = __halves2half2(l0, l1);
    }
}

// ---------------- k_finalize: reduce stats partials, zero flags ----------
__global__ void k_finalize() {
    __shared__ double sh[256];
    __shared__ double sh2[256];
    int t = threadIdx.x;
    sh[t] = g_ps[t]; sh2[t] = g_ps2[t];
    __syncthreads();
    for (int o = 128; o > 0; o >>= 1) {
        if (t < o) { sh[t] += sh[t + o]; sh2[t] += sh2[t + o]; }
        __syncthreads();
    }
    if (t == 0) {
        double n = (double)NELEM;
        double mean = sh[0] / n;
        double var  = (sh2[0] - sh[0] * sh[0] / n) / (n - 1.0);
        g_mean = (float)mean;
        g_std  = (float)sqrt(var);
    }
    if (t < 16) g_flag[t] = 0;
}

// ---------------- fuse1: stats (256 blocks) || wsplit[0, WS_F1) ---------
__global__ void k_fuse1(const float* __restrict__ xp,
                        const float* __restrict__ w2) {
    __shared__ float scratch[64 * 33];
    const int bx = blockIdx.x;
    if (bx < 256) {
        double s = 0.0, s2 = 0.0;
        for (size_t i = (size_t)bx * blockDim.x + threadIdx.x; i < NELEM;
             i += (size_t)256 * blockDim.x) {
            float v = xp[i];
            s  += (double)v;
            s2 += (double)v * (double)v;
        }
        double* sh  = (double*)scratch;
        double* sh2 = (double*)scratch + 256;
        sh[threadIdx.x] = s; sh2[threadIdx.x] = s2;
        __syncthreads();
        for (int o = 128; o > 0; o >>= 1) {
            if (threadIdx.x < o) {
                sh[threadIdx.x]  += sh[threadIdx.x + o];
                sh2[threadIdx.x] += sh2[threadIdx.x + o];
            }
            __syncthreads();
        }
        if (threadIdx.x == 0) {
            g_ps[bx]  = sh[0];
            g_ps2[bx] = sh2[0];
        }
    } else {
        wsplit_body(w2, bx - 256, scratch);
    }
}

// ---------------- fuse2: xnsplit (512) || w1split (1024) || wsplit ------
__global__ void k_fuse2(const float* __restrict__ xp,
                        const float* __restrict__ w1,
                        const float* __restrict__ w2) {
    __shared__ float scratch[64 * 33];
    const int bx = blockIdx.x;
    if (bx < 512) {
        float mean = g_mean;
        float inv  = 1.0f / g_std;
        const float4* src = (const float4*)xp;
        for (size_t i = (size_t)bx * blockDim.x + threadIdx.x;
             i < NELEM / 4; i += (size_t)512 * blockDim.x) {
            float4 v = src[i];
            v.x = (v.x - mean) * inv; v.y = (v.y - mean) * inv;
            v.z = (v.z - mean) * inv; v.w = (v.w - mean) * inv;
            __half h0 = __float2half_rn(v.x), h1 = __float2half_rn(v.y);
            __half h2 = __float2half_rn(v.z), h3 = __float2half_rn(v.w);
            __half l0 = __float2half_rn((v.x - __half2float(h0)) * LO_SCALE);
            __half l1 = __float2half_rn((v.y - __half2float(h1)) * LO_SCALE);
            __half l2 = __float2half_rn((v.z - __half2float(h2)) * LO_SCALE);
            __half l3 = __float2half_rn((v.w - __half2float(h3)) * LO_SCALE);
            __half2 hv[2] = {__halves2half2(h0, h1), __halves2half2(h2, h3)};
            __half2 lv[2] = {__halves2half2(l0, l1), __halves2half2(l2, l3)};
            ((uint2*)g_XNh)[i] = *(uint2*)hv;
            ((uint2*)g_XNl)[i] = *(uint2*)lv;
        }
    } else if (bx < 512 + 1024) {
        const int wb = bx - 512;
        const int n0 = (wb & 15) * 32, k0 = (wb >> 4) * 64;
        const int tid = threadIdx.x;
#pragma unroll
        for (int p = 0; p < 8; p++) {
            int idx = tid + p * 256;
            int kr = idx >> 5, nc = idx & 31;
            scratch[kr * 33 + nc] = w1[(size_t)(k0 + kr) * HID + n0 + nc];
        }
        __syncthreads();
#pragma unroll
        for (int p = 0; p < 4; p++) {
            int idx = tid + p * 256;
            int n = idx >> 5, kp = idx & 31;
            float v0 = scratch[(2 * kp) * 33 + n];
            float v1 = scratch[(2 * kp + 1) * 33 + n];
            __half h0 = __float2half_rn(v0);
            __half h1 = __float2half_rn(v1);
            __half l0 = __float2half_rn((v0 - __half2float(h0)) * LO_SCALE);
            __half l1 = __float2half_rn((v1 - __half2float(h1)) * LO_SCALE);
            size_t o = ((size_t)(n0 + n) * S_IN + k0 + 2 * kp) >> 1;
            ((__half2*)g_W1h)[o] = __halves2half2(h0, h1);
            ((__half2*)g_W1l)[o] = __halves2half2(l0, l1);
        }
    } else {
        wsplit_body(w2, (bx - 1536) + WS_F1, scratch);
    }
}

// ---------------- mma.sync helpers ---------------------------------------
#define SWZ128(x) ((x) ^ (((x) >> 3) & 0x70))

#define LDSM4(r, addr)                                                        \
    asm volatile("ldmatrix.sync.aligned.m8n8.x4.shared.b16 {%0,%1,%2,%3}, [%4];" \
                 : "=r"((r)[0]), "=r"((r)[1]), "=r"((r)[2]), "=r"((r)[3])     \
                 : "r"(addr))

#define MMA16816(d, a, b)                                                     \
    asm volatile("mma.sync.aligned.m16n8k16.row.col.f32.f16.f16.f32 "         \
                 "{%0,%1,%2,%3},{%4,%5,%6,%7},{%8,%9},{%0,%1,%2,%3};"         \
                 : "+f"((d)[0]), "+f"((d)[1]), "+f"((d)[2]), "+f"((d)[3])     \
                 : "r"((a)[0]), "r"((a)[1]), "r"((a)[2]), "r"((a)[3]),        \
                   "r"((b)[0]), "r"((b)[1]))

#define CP16(dst, src)                                                        \
    asm volatile("cp.async.cg.shared.global [%0], [%1], 16;" :: "r"(dst), "l"(src))

// GEMM1 region inside the shared 112KB smem: 4 stages x 16KB
#define STG1    16384
#define B1_OFF  8192
// GEMM2: 4 stages x 28KB. Stage rows are 128B = [hi 64B | lo 64B].
#define STAGE   28672
#define B_SOFF  16384
#define SMEMSZ  (4 * STAGE)   // 114688
#define EPIT    98            // epilogue plane pitch (floats)

// ---------------- combined kernel: gemm1 (blocks 0-127) + gemm2 ---------
// gemm1 publishes per-m-tile completion flags; gemm2 CTAs spin until the
// two 64-row tiles covering their 128-row A block are ready. Safe: all
// 128 gemm1 blocks fit in scheduling wave 1 (296 CTA slots).
__global__ __launch_bounds__(256, 2)
void k_gemm12(const float* __restrict__ b1, const float* __restrict__ b2,
              const float* __restrict__ x_in, const float* __restrict__ ps,
              float* __restrict__ out_phi) {
    extern __shared__ char sm2[];
    const uint32_t sb = (uint32_t)__cvta_generic_to_shared(sm2);
    const int tid  = threadIdx.x;
    const int wid  = tid >> 5;
    const int lane = tid & 31;

    if (blockIdx.x < 128) {
        // ================= GEMM1: H = tanh(xn @ w1 + b1) =================
        const int bxf = blockIdx.x;
        const int warp_m = wid & 1;
        const int warp_n = wid >> 1;
        const int m0 = (bxf & 15) * 64;
        const int n0 = (bxf >> 4) * 64;

        float accm[4][4], accc[4][4];
#pragma unroll
        for (int t = 0; t < 4; t++)
#pragma unroll
            for (int j = 0; j < 4; j++) { accm[t][j] = 0.f; accc[t][j] = 0.f; }

#define ISSUE1(KC)                                                             \
    do {                                                                       \
        const int k0_ = (KC) * 32;                                             \
        const uint32_t st_ = sb + ((KC) & 3) * STG1;                           \
        _Pragma("unroll")                                                      \
        for (int p_ = 0; p_ < 2; p_++) {          /* A: 512 16B chunks */      \
            int c_ = tid + p_ * 256;                                           \
            int r_ = c_ >> 3, q_ = c_ & 7;                                     \
            const __half* src_ = ((q_ >> 2) ? g_XNl : g_XNh) +                 \
                                 (size_t)(m0 + r_) * S_IN + k0_ + (q_ & 3) * 8;\
            CP16(st_ + SWZ128((uint32_t)(r_ * 128 + q_ * 16)), src_);          \
        }                                                                      \
        _Pragma("unroll")                                                      \
        for (int p_ = 0; p_ < 2; p_++) {          /* B: 512 16B chunks */      \
            int c_ = tid + p_ * 256;                                           \
            int r_ = c_ >> 3, q_ = c_ & 7;                                     \
            const __half* src_ = ((q_ >> 2) ? g_W1l : g_W1h) +                 \
                                 (size_t)(n0 + r_) * S_IN + k0_ + (q_ & 3) * 8;\
            CP16(st_ + B1_OFF + SWZ128((uint32_t)(r_ * 128 + q_ * 16)), src_); \
        }                                                                      \
        asm volatile("cp.async.commit_group;" ::: "memory");                   \
    } while (0)

        ISSUE1(0); ISSUE1(1); ISSUE1(2);

        for (int kc = 0; kc < 128; kc++) {
            if (kc < 126) asm volatile("cp.async.wait_group 2;" ::: "memory");
            else          asm volatile("cp.async.wait_group 0;" ::: "memory");
            __syncthreads();
            if (kc < 125) ISSUE1(kc + 3);

            const uint32_t abase = sb + (kc & 3) * STG1;
            const uint32_t bbase = abase + B1_OFF;

#pragma unroll
            for (int ks = 0; ks < 2; ks++) {
                uint32_t af[2][2][4];
#pragma unroll
                for (int s = 0; s < 2; s++)
#pragma unroll
                    for (int mi = 0; mi < 2; mi++) {
                        int row = warp_m * 32 + mi * 16 + (lane & 15);
                        int off = row * 128 + s * 64 + ks * 32 + (lane >> 4) * 16;
                        LDSM4(af[s][mi], abase + SWZ128(off));
                    }
#pragma unroll
                for (int s = 0; s < 2; s++) {
                    uint32_t bf[2][2];
                    {
                        int row = warp_n * 16 + (lane & 7) + ((lane >> 4) & 1) * 8;
                        int off = row * 128 + s * 64 + ks * 32 + ((lane >> 3) & 1) * 16;
                        uint32_t q[4];
                        LDSM4(q, bbase + SWZ128(off));
                        bf[0][0] = q[0]; bf[0][1] = q[1];
                        bf[1][0] = q[2]; bf[1][1] = q[3];
                    }
                    if (s == 0) {
#pragma unroll
                        for (int mi = 0; mi < 2; mi++)
#pragma unroll
                            for (int nj = 0; nj < 2; nj++)
                                MMA16816(accm[mi * 2 + nj], af[0][mi], bf[nj]);
#pragma unroll
                        for (int mi = 0; mi < 2; mi++)
#pragma unroll
                            for (int nj = 0; nj < 2; nj++)
                                MMA16816(accc[mi * 2 + nj], af[1][mi], bf[nj]);
                    } else {
#pragma unroll
                        for (int mi = 0; mi < 2; mi++)
#pragma unroll
                            for (int nj = 0; nj < 2; nj++)
                                MMA16816(accc[mi * 2 + nj], af[0][mi], bf[nj]);
                    }
                }
            }
        }

        // epilogue: tanh + fp16 split
#pragma unroll
        for (int mi = 0; mi < 2; mi++)
#pragma unroll
            for (int nj = 0; nj < 2; nj++) {
                int t = mi * 2 + nj;
                int r0 = m0 + warp_m * 32 + mi * 16 + (lane >> 2);
                int c0 = n0 + warp_n * 16 + nj * 8 + (lane & 3) * 2;
                float ba = b1[c0], bb = b1[c0 + 1];
                float t0 = tanhf(accm[t][0] + fmaf(accc[t][0], LO_INVF, ba));
                float t1 = tanhf(accm[t][1] + fmaf(accc[t][1], LO_INVF, bb));
                float t2 = tanhf(accm[t][2] + fmaf(accc[t][2], LO_INVF, ba));
                float t3 = tanhf(accm[t][3] + fmaf(accc[t][3], LO_INVF, bb));
                __half h0 = __float2half_rn(t0), h1 = __float2half_rn(t1);
                __half h2 = __float2half_rn(t2), h3 = __float2half_rn(t3);
                __half l0 = __float2half_rn((t0 - __half2float(h0)) * LO_SCALE);
                __half l1 = __float2half_rn((t1 - __half2float(h1)) * LO_SCALE);
                __half l2 = __float2half_rn((t2 - __half2float(h2)) * LO_SCALE);
                __half l3 = __float2half_rn((t3 - __half2float(h3)) * LO_SCALE);
                size_t oa = ((size_t)r0 * HID + c0) >> 1;
                size_t ob = ((size_t)(r0 + 8) * HID + c0) >> 1;
                ((__half2*)g_Ah)[oa] = __halves2half2(h0, h1);
                ((__half2*)g_Ah)[ob] = __halves2half2(h2, h3);
                ((__half2*)g_Al)[oa] = __halves2half2(l0, l1);
                ((__half2*)g_Al)[ob] = __halves2half2(l2, l3);
            }
        __threadfence();
        __syncthreads();
        if (tid == 0) atomicAdd(&g_flag[bxf & 15], 1);
        return;
#undef ISSUE1
    }

    // ==================== GEMM2 + fused spline epilogue ====================
    const int e   = blockIdx.x - 128;
    const int bxm = e & 7;            // m fastest (w2 L2 reuse)
    const int byn = e >> 3;
    const int m0 = bxm * 128;
    const int n0 = byn * 96;
    const int warp_m = wid & 3;
    const int warp_n = wid >> 2;

    // wait for the two gemm1 m-tiles covering rows [m0, m0+128)
    if (tid == 0) {
        volatile int* vf = (volatile int*)g_flag;
        while (vf[2 * bxm] < 8 || vf[2 * bxm + 1] < 8) {}
    }
    __syncthreads();
    __threadfence();

    float accm[12][4], accc[12][4];
#pragma unroll
    for (int t = 0; t < 12; t++)
#pragma unroll
        for (int j = 0; j < 4; j++) { accm[t][j] = 0.f; accc[t][j] = 0.f; }

#define ISSUE(KC)                                                              \
    do {                                                                       \
        const int k0_ = (KC) * 32;                                             \
        const uint32_t st_ = sb + ((KC) & 3) * STAGE;                          \
        _Pragma("unroll")                                                      \
        for (int p_ = 0; p_ < 4; p_++) {          /* A: 1024 16B chunks */     \
            int c_ = tid + p_ * 256;                                           \
            int r_ = c_ >> 3, q_ = c_ & 7;                                     \
            const __half* src_ = ((q_ >> 2) ? g_Al : g_Ah) +                   \
                                 (size_t)(m0 + r_) * HID + k0_ + (q_ & 3) * 8; \
            uint32_t off_ = (uint32_t)(r_ * 128 + q_ * 16);                    \
            CP16(st_ + SWZ128(off_), src_);                                    \
        }                                                                      \
        _Pragma("unroll")                                                      \
        for (int p_ = 0; p_ < 3; p_++) {          /* B: 768 16B chunks */      \
            int c_ = tid + p_ * 256;                                           \
            int r_ = c_ >> 3, q_ = c_ & 7;                                     \
            const __half* src_ = ((q_ >> 2) ? g_Bl : g_Bh) +                   \
                                 (size_t)(n0 + r_) * HID + k0_ + (q_ & 3) * 8; \
            uint32_t off_ = (uint32_t)(r_ * 128 + q_ * 16);                    \
            CP16(st_ + B_SOFF + SWZ128(off_), src_);                           \
        }                                                                      \
        asm volatile("cp.async.commit_group;" ::: "memory");                   \
    } while (0)

    ISSUE(0); ISSUE(1); ISSUE(2);

    for (int kc = 0; kc < 16; kc++) {
        asm volatile("cp.async.wait_group 2;" ::: "memory");
        __syncthreads();
        if (kc < 13) ISSUE(kc + 3);

        const uint32_t abase = sb + (kc & 3) * STAGE;
        const uint32_t bbase = abase + B_SOFF;

#pragma unroll
        for (int ks = 0; ks < 2; ks++) {
            uint32_t af[2][2][4];
#pragma unroll
            for (int s = 0; s < 2; s++)
#pragma unroll
                for (int mi = 0; mi < 2; mi++) {
                    int row = warp_m * 32 + mi * 16 + (lane & 15);
                    int off = row * 128 + s * 64 + ks * 32 + (lane >> 4) * 16;
                    LDSM4(af[s][mi], abase + SWZ128(off));
                }
#pragma unroll
            for (int s = 0; s < 2; s++) {
                uint32_t bf[6][2];
#pragma unroll
                for (int j = 0; j < 3; j++) {
                    int row = warp_n * 48 + j * 16 + (lane & 7) + ((lane >> 4) & 1) * 8;
                    int off = row * 128 + s * 64 + ks * 32 + ((lane >> 3) & 1) * 16;
                    uint32_t q[4];
                    LDSM4(q, bbase + SWZ128(off));
                    bf[2 * j][0] = q[0]; bf[2 * j][1] = q[1];
                    bf[2 * j + 1][0] = q[2]; bf[2 * j + 1][1] = q[3];
                }
                if (s == 0) {
#pragma unroll
                    for (int mi = 0; mi < 2; mi++)
#pragma unroll
                        for (int nj = 0; nj < 6; nj++)
                            MMA16816(accm[mi * 6 + nj], af[0][mi], bf[nj]);
#pragma unroll
                    for (int mi = 0; mi < 2; mi++)
#pragma unroll
                        for (int nj = 0; nj < 6; nj++)
                            MMA16816(accc[mi * 6 + nj], af[1][mi], bf[nj]);
                } else {
#pragma unroll
                    for (int mi = 0; mi < 2; mi++)
#pragma unroll
                        for (int nj = 0; nj < 6; nj++)
                            MMA16816(accc[mi * 6 + nj], af[0][mi], bf[nj]);
                }
            }
        }
    }
    __syncthreads();

    // ---- epilogue: exchange fragments through SMEM, then spline ----
    float* mp = (float*)sm2;               // main plane [128][EPIT]
    float* cpl = (float*)sm2 + 128 * EPIT; // corr plane
#pragma unroll
    for (int mi = 0; mi < 2; mi++)
#pragma unroll
        for (int nj = 0; nj < 6; nj++) {
            int t = mi * 6 + nj;
            int row = warp_m * 32 + mi * 16 + (lane >> 2);
            int col = warp_n * 48 + nj * 8 + (lane & 3) * 2;
            *(float2*)&mp[row * EPIT + col]        = make_float2(accm[t][0], accm[t][1]);
            *(float2*)&mp[(row + 8) * EPIT + col]  = make_float2(accm[t][2], accm[t][3]);
            *(float2*)&cpl[row * EPIT + col]       = make_float2(accc[t][0], accc[t][1]);
            *(float2*)&cpl[(row + 8) * EPIT + col] = make_float2(accc[t][2], accc[t][3]);
        }
    __syncthreads();

    const float psv = ps[0];

#pragma unroll 1
    for (int it = 0; it < 2; it++) {
        int idx = tid + it * 256;          // 512 (b,s) pairs
        int m   = idx >> 2;                // 0..127
        int grp = idx & 3;                 // 0..3
        const int b = m0 + m;
        const int s_glob = byn * 4 + grp;
        const int cb = s_glob * 24;
        const int base = m * EPIT + grp * 24;

        float v[16];
#pragma unroll
        for (int cc = 0; cc < 16; cc++) {
            float arg = mp[base + cc] + fmaf(cpl[base + cc], LO_INVF, b2[cb + cc]);
            v[cc] = ftanh(arg);
        }

        float hm = v[0], wm = v[8];
#pragma unroll
        for (int i = 1; i < KNOT; i++) {
            hm = fmaxf(hm, v[i]);
            wm = fmaxf(wm, v[8 + i]);
        }
        float he[KNOT], we[KNOT];
        float hs = 0.f, ws = 0.f;
#pragma unroll
        for (int i = 0; i < KNOT; i++) {
            he[i] = fexp(v[i] - hm);      hs += he[i];
            we[i] = fexp(v[8 + i] - wm);  ws += we[i];
        }
        float hscale = TWO_PI_F / hs;
        float wscale = TWO_PI_F / ws;
        float h[KNOT], w[KNOT];
#pragma unroll
        for (int i = 0; i < KNOT; i++) {
            h[i] = he[i] * hscale;
            w[i] = we[i] * wscale;
        }

        const float x = x_in[(size_t)b * S_OUTD + s_glob];

        int kc2 = 0;
        ff2 cw = {0.f, 0.f};
#pragma unroll
        for (int i = 0; i < KNOT; i++) {
            cw = ff_addf(cw, w[i]);
            kc2 += (((cw.hi - x) + cw.lo) < 0.f) ? 1 : 0;
        }
        int ki = kc2 < (KNOT - 1) ? kc2 : (KNOT - 1);
        int kn = (ki + 1) & (KNOT - 1);

        float w_k = 0.f, h_k = 0.f;
        ff2 x_km1 = {0.f, 0.f}, phi_km1 = {0.f, 0.f};
        ff2 pw = {0.f, 0.f}, ph = {0.f, 0.f};
#pragma unroll
        for (int i = 0; i < KNOT; i++) {
            if (i == ki) {
                w_k = w[i]; h_k = h[i];
                if (i == 0) { x_km1.hi = -EPS_F; x_km1.lo = 0.f; }
                else        { x_km1 = pw; }
                phi_km1 = ph;
            }
            pw = ff_addf(pw, w[i]);
            ph = ff_addf(ph, h[i]);
        }

        float dr0 = ftanh(mp[base + 16 + ki] +
                          fmaf(cpl[base + 16 + ki], LO_INVF, b2[cb + 16 + ki]));
        float dr1 = ftanh(mp[base + 16 + kn] +
                          fmaf(cpl[base + 16 + kn], LO_INVF, b2[cb + 16 + kn]));
        float d_k   = log1pf(fexp(dr0));
        float d_kp1 = log1pf(fexp(dr1));

        float s_k   = h_k / w_k;
        float alpha = ((x - x_km1.hi) - x_km1.lo) / w_k;
        float a1m   = alpha * (1.f - alpha);
        float denom = s_k + (d_kp1 + d_k - 2.f * s_k) * a1m;
        float frac  = h_k * fmaf(s_k * alpha, alpha, d_k * a1m) / denom;

        ff2 phif = ff_addf(phi_km1, frac);
        phif = ff_addf(phif, psv);
        float phiv = phif.hi + phif.lo;
        if (phiv >= TWO_PI_F) phiv -= TWO_PI_F;
        if (phiv >= TWO_PI_F) phiv -= TWO_PI_F;
        if (phiv < 0.f) phiv += TWO_PI_F;
        out_phi[(size_t)b * S_OUTD + s_glob] = phiv;

        float om   = 1.f - alpha;
        float grad = s_k * s_k *
                     fmaf(d_kp1 * alpha, alpha, fmaf(2.f * s_k, a1m, d_k * om * om)) /
                     (denom * denom);
        float lgv = logf(grad);
        lgv += __shfl_xor_sync(0xffffffffu, lgv, 1);
        lgv += __shfl_xor_sync(0xffffffffu, lgv, 2);
        if (grp == 0)
            g_part[(size_t)b * 1024 + byn] = lgv;
    }
#undef ISSUE
}

// ---------------- kernel: deterministic log-density reduction ----------
__global__ void k_ldsum(const float* __restrict__ ld_in,
                        float* __restrict__ out_ld) {
    __shared__ double sh[256];
    int b = blockIdx.x;
    double sm = 0.0;
    for (int i = threadIdx.x; i < 1024; i += 256)
        sm += (double)g_part[(size_t)b * 1024 + i];
    sh[threadIdx.x] = sm;
    __syncthreads();
    for (int o = 128; o > 0; o >>= 1) {
        if (threadIdx.x < o) sh[threadIdx.x] += sh[threadIdx.x + o];
        __syncthreads();
    }
    if (threadIdx.x == 0) out_ld[b] = (float)((double)ld_in[b] - sh[0]);
}

// ---------------- launcher ----------------------------------------------
extern "C" void kernel_launch(void* const* d_in, const int* in_sizes, int n_in,
                              void* d_out, int out_size) {
    const float* x_in      = (const float*)d_in[0];
    const float* x_passive = (const float*)d_in[1];
    const float* ld_in     = (const float*)d_in[2];
    const float* w1        = (const float*)d_in[3];
    const float* b1        = (const float*)d_in[4];
    const float* w2        = (const float*)d_in[5];
    const float* b2        = (const float*)d_in[6];
    const float* ps        = (const float*)d_in[7];
    (void)in_sizes; (void)n_in; (void)out_size;

    float* out_phi = (float*)d_out;
    float* out_ld  = (float*)d_out + (size_t)B_DIM * S_OUTD;

    cudaFuncSetAttribute(k_gemm12, cudaFuncAttributeMaxDynamicSharedMemorySize,
                         SMEMSZ);

    k_fuse1<<<256 + WS_F1, 256>>>(x_passive, w2);
    k_finalize<<<1, 256>>>();
    k_fuse2<<<512 + 1024 + WS_F2, 256>>>(x_passive, w1, w2);
    k_gemm12<<<128 + (B_DIM / 128) * (NCOL / 96), 256, SMEMSZ>>>(
        b1, b2, x_in, ps, out_phi);
    k_ldsum<<<B_DIM, 256>>>(ld_in, out_ld);
}

// round 15
// speedup vs baseline: 1.0492x; 1.0492x over previous
#include <cuda_runtime.h>
#include <cuda_fp16.h>
#include <cstdint>
#include <math.h>

// Problem constants
#define B_DIM   1024
#define S_IN    4096
#define S_OUTD  4096
#define KNOT    8
#define HID     512
#define NCOL    (S_OUTD * 3 * KNOT)    // 98304
#define NELEM   ((size_t)B_DIM * S_IN) // 4194304
#define TWO_PI_F 6.28318530717958647692f
#define EPS_F    1e-6f
#define LO_SCALE 2048.0f
#define LO_INVF  (1.0f / 2048.0f)

// wsplit partition: 24576 blocks total, split across fuse1/fuse2 only
#define WS_TOTAL 24576
#define WS_F1    12288
#define WS_F2    (WS_TOTAL - WS_F1)    // 12288

// ---------------- device scratch (static, no allocation) ----------------
static __device__ double g_sum;
static __device__ double g_sumsq;
static __device__ float  g_mean;
static __device__ float  g_std;
static __device__ __align__(16) float g_part[(size_t)B_DIM * 1024];  // 4 MB
// fp16 2-way splits (lo pre-scaled by 2048)
static __device__ __align__(16) __half g_XNh[NELEM];                // xn
static __device__ __align__(16) __half g_XNl[NELEM];
static __device__ __align__(16) __half g_W1h[(size_t)HID * S_IN];   // w1^T
static __device__ __align__(16) __half g_W1l[(size_t)HID * S_IN];
static __device__ __align__(16) __half g_Ah[B_DIM * HID];           // H
static __device__ __align__(16) __half g_Al[B_DIM * HID];
static __device__ __align__(16) __half g_Bh[(size_t)NCOL * HID];    // w2^T
static __device__ __align__(16) __half g_Bl[(size_t)NCOL * HID];

// ---------------- FMA-pipe transcendentals (avoid MUFU) ------------------
static __device__ __forceinline__ float fexp(float x) {
    float t = x * 1.4426950408889634f;          // log2(e)
    float n = rintf(t);
    float f = fmaf(n, -0.693359375f, x);        // ln2 hi
    f = fmaf(n, 2.12194440e-4f, f);             // ln2 lo
    float p = 1.9841269841e-4f;
    p = fmaf(p, f, 1.3888888889e-3f);
    p = fmaf(p, f, 8.3333333333e-3f);
    p = fmaf(p, f, 4.1666666667e-2f);
    p = fmaf(p, f, 1.6666666667e-1f);
    p = fmaf(p, f, 0.5f);
    p = fmaf(p, f, 1.0f);
    p = fmaf(p, f, 1.0f);
    int j = (int)n;
    float s = __int_as_float((j + 127) << 23);
    return p * s;
}

static __device__ __forceinline__ float ftanh(float x) {
    float a = fminf(fabsf(x), 9.0f);
    float e = fexp(-2.0f * a);
    float d = 1.0f + e;
    float r;
    asm("rcp.approx.f32 %0, %1;" : "=f"(r) : "f"(d));
    r = r * (2.0f - d * r);
    float tt = (1.0f - e) * r;
    return copysignf(tt, x);
}

// ---------------- float-float (TwoSum) helpers ---------------------------
struct ff2 { float hi, lo; };
static __device__ __forceinline__ ff2 ff_renorm(float s, float e) {
    float t = s + e;
    return {t, e - (t - s)};
}
static __device__ __forceinline__ ff2 ff_addf(ff2 a, float b) {
    float s  = a.hi + b;
    float bb = s - a.hi;
    float err = (a.hi - (s - bb)) + (b - bb);
    return ff_renorm(s, err + a.lo);
}

// ---------------- wsplit body (shared by the fused kernels) -------------
static __device__ __forceinline__ void wsplit_body(const float* __restrict__ w2,
                                                   int wb, float* scratch) {
    const int n0 = (wb % 3072) * 32;
    const int k0 = (wb / 3072) * 64;
    const int tid = threadIdx.x;
#pragma unroll
    for (int p = 0; p < 8; p++) {
        int idx = tid + p * 256;
        int kr = idx >> 5, nc = idx & 31;
        scratch[kr * 33 + nc] = w2[(size_t)(k0 + kr) * NCOL + n0 + nc];
    }
    __syncthreads();
#pragma unroll
    for (int p = 0; p < 4; p++) {
        int idx = tid + p * 256;
        int n = idx >> 5, kp = idx & 31;
        float v0 = scratch[(2 * kp) * 33 + n];
        float v1 = scratch[(2 * kp + 1) * 33 + n];
        __half h0 = __float2half_rn(v0);
        __half h1 = __float2half_rn(v1);
        __half l0 = __float2half_rn((v0 - __half2float(h0)) * LO_SCALE);
        __half l1 = __float2half_rn((v1 - __half2float(h1)) * LO_SCALE);
        size_t o = ((size_t)(n0 + n) * HID + k0 + 2 * kp) >> 1;
        ((__half2*)g_Bh)[o] = __halves2half2(h0, h1);
        ((__half2*)g_Bl)[o] = __halves2half2(l0, l1);
    }
}

// ---------------- small kernels -----------------------------------------
__global__ void k_zero() {
    if (threadIdx.x == 0) { g_sum = 0.0; g_sumsq = 0.0; }
}

__global__ void k_finalize() {
    if (threadIdx.x == 0) {
        double n = (double)NELEM;
        double mean = g_sum / n;
        double var  = (g_sumsq - g_sum * g_sum / n) / (n - 1.0);
        g_mean = (float)mean;
        g_std  = (float)sqrt(var);
    }
}

// ---------------- fuse1: stats (256 blocks) || wsplit[0, WS_F1) ---------
__global__ void k_fuse1(const float* __restrict__ xp,
                        const float* __restrict__ w2) {
    __shared__ float scratch[64 * 33];
    const int bx = blockIdx.x;
    if (bx < 256) {
        double s = 0.0, s2 = 0.0;
        for (size_t i = (size_t)bx * blockDim.x + threadIdx.x; i < NELEM;
             i += (size_t)256 * blockDim.x) {
            float v = xp[i];
            s  += (double)v;
            s2 += (double)v * (double)v;
        }
        double* sh  = (double*)scratch;
        double* sh2 = (double*)scratch + 256;
        sh[threadIdx.x] = s; sh2[threadIdx.x] = s2;
        __syncthreads();
        for (int o = 128; o > 0; o >>= 1) {
            if (threadIdx.x < o) {
                sh[threadIdx.x]  += sh[threadIdx.x + o];
                sh2[threadIdx.x] += sh2[threadIdx.x + o];
            }
            __syncthreads();
        }
        if (threadIdx.x == 0) {
            atomicAdd(&g_sum,  sh[0]);
            atomicAdd(&g_sumsq, sh2[0]);
        }
    } else {
        wsplit_body(w2, bx - 256, scratch);
    }
}

// ---------------- fuse2: xnsplit (512) || w1split (1024) || wsplit ------
__global__ void k_fuse2(const float* __restrict__ xp,
                        const float* __restrict__ w1,
                        const float* __restrict__ w2) {
    __shared__ float scratch[64 * 33];
    const int bx = blockIdx.x;
    if (bx < 512) {
        float mean = g_mean;
        float inv  = 1.0f / g_std;
        const float4* src = (const float4*)xp;
        for (size_t i = (size_t)bx * blockDim.x + threadIdx.x;
             i < NELEM / 4; i += (size_t)512 * blockDim.x) {
            float4 v = src[i];
            v.x = (v.x - mean) * inv; v.y = (v.y - mean) * inv;
            v.z = (v.z - mean) * inv; v.w = (v.w - mean) * inv;
            __half h0 = __float2half_rn(v.x), h1 = __float2half_rn(v.y);
            __half h2 = __float2half_rn(v.z), h3 = __float2half_rn(v.w);
            __half l0 = __float2half_rn((v.x - __half2float(h0)) * LO_SCALE);
            __half l1 = __float2half_rn((v.y - __half2float(h1)) * LO_SCALE);
            __half l2 = __float2half_rn((v.z - __half2float(h2)) * LO_SCALE);
            __half l3 = __float2half_rn((v.w - __half2float(h3)) * LO_SCALE);
            __half2 hv[2] = {__halves2half2(h0, h1), __halves2half2(h2, h3)};
            __half2 lv[2] = {__halves2half2(l0, l1), __halves2half2(l2, l3)};
            ((uint2*)g_XNh)[i] = *(uint2*)hv;
            ((uint2*)g_XNl)[i] = *(uint2*)lv;
        }
    } else if (bx < 512 + 1024) {
        const int wb = bx - 512;
        const int n0 = (wb & 15) * 32, k0 = (wb >> 4) * 64;
        const int tid = threadIdx.x;
#pragma unroll
        for (int p = 0; p < 8; p++) {
            int idx = tid + p * 256;
            int kr = idx >> 5, nc = idx & 31;
            scratch[kr * 33 + nc] = w1[(size_t)(k0 + kr) * HID + n0 + nc];
        }
        __syncthreads();
#pragma unroll
        for (int p = 0; p < 4; p++) {
            int idx = tid + p * 256;
            int n = idx >> 5, kp = idx & 31;
            float v0 = scratch[(2 * kp) * 33 + n];
            float v1 = scratch[(2 * kp + 1) * 33 + n];
            __half h0 = __float2half_rn(v0);
            __half h1 = __float2half_rn(v1);
            __half l0 = __float2half_rn((v0 - __half2float(h0)) * LO_SCALE);
            __half l1 = __float2half_rn((v1 - __half2float(h1)) * LO_SCALE);
            size_t o = ((size_t)(n0 + n) * S_IN + k0 + 2 * kp) >> 1;
            ((__half2*)g_W1h)[o] = __halves2half2(h0, h1);
            ((__half2*)g_W1l)[o] = __halves2half2(l0, l1);
        }
    } else {
        wsplit_body(w2, (bx - 1536) + WS_F1, scratch);
    }
}

// ---------------- mma.sync helpers ---------------------------------------
#define SWZ128(x) ((x) ^ (((x) >> 3) & 0x70))

#define LDSM4(r, addr)                                                        \
    asm volatile("ldmatrix.sync.aligned.m8n8.x4.shared.b16 {%0,%1,%2,%3}, [%4];" \
                 : "=r"((r)[0]), "=r"((r)[1]), "=r"((r)[2]), "=r"((r)[3])     \
                 : "r"(addr))

#define MMA16816(d, a, b)                                                     \
    asm volatile("mma.sync.aligned.m16n8k16.row.col.f32.f16.f16.f32 "         \
                 "{%0,%1,%2,%3},{%4,%5,%6,%7},{%8,%9},{%0,%1,%2,%3};"         \
                 : "+f"((d)[0]), "+f"((d)[1]), "+f"((d)[2]), "+f"((d)[3])     \
                 : "r"((a)[0]), "r"((a)[1]), "r"((a)[2]), "r"((a)[3]),        \
                   "r"((b)[0]), "r"((b)[1]))

#define CP16(dst, src)                                                        \
    asm volatile("cp.async.cg.shared.global [%0], [%1], 16;" :: "r"(dst), "l"(src))

// ---------------- k_gemm1m: GEMM1 (128 blocks, 64x64 tile), uncontended -
// CTA: M=64 x N=64, K=4096 in 128 chunks of 32, 4 stages, occ 2.
// 8 warps as 2(m) x 4(n): warp tile 32 x 16.
#define STG1    16384
#define B1_OFF  8192
#define SM1SZ   (4 * STG1)   // 65536

__global__ __launch_bounds__(256, 2)
void k_gemm1m(const float* __restrict__ b1) {
    extern __shared__ char sm1[];
    const int bxf = blockIdx.x;
    const uint32_t sb = (uint32_t)__cvta_generic_to_shared(sm1);
    const int tid  = threadIdx.x;
    const int wid  = tid >> 5;
    const int lane = tid & 31;
    const int warp_m = wid & 1;
    const int warp_n = wid >> 1;
    const int m0 = (bxf & 15) * 64;
    const int n0 = (bxf >> 4) * 64;

    float accm[4][4], accc[4][4];
#pragma unroll
    for (int t = 0; t < 4; t++)
#pragma unroll
        for (int j = 0; j < 4; j++) { accm[t][j] = 0.f; accc[t][j] = 0.f; }

#define ISSUE1(KC)                                                             \
    do {                                                                       \
        const int k0_ = (KC) * 32;                                             \
        const uint32_t st_ = sb + ((KC) & 3) * STG1;                           \
        _Pragma("unroll")                                                      \
        for (int p_ = 0; p_ < 2; p_++) {          /* A: 512 16B chunks */      \
            int c_ = tid + p_ * 256;                                           \
            int r_ = c_ >> 3, q_ = c_ & 7;                                     \
            const __half* src_ = ((q_ >> 2) ? g_XNl : g_XNh) +                 \
                                 (size_t)(m0 + r_) * S_IN + k0_ + (q_ & 3) * 8;\
            CP16(st_ + SWZ128((uint32_t)(r_ * 128 + q_ * 16)), src_);          \
        }                                                                      \
        _Pragma("unroll")                                                      \
        for (int p_ = 0; p_ < 2; p_++) {          /* B: 512 16B chunks */      \
            int c_ = tid + p_ * 256;                                           \
            int r_ = c_ >> 3, q_ = c_ & 7;                                     \
            const __half* src_ = ((q_ >> 2) ? g_W1l : g_W1h) +                 \
                                 (size_t)(n0 + r_) * S_IN + k0_ + (q_ & 3) * 8;\
            CP16(st_ + B1_OFF + SWZ128((uint32_t)(r_ * 128 + q_ * 16)), src_); \
        }                                                                      \
        asm volatile("cp.async.commit_group;" ::: "memory");                   \
    } while (0)

    ISSUE1(0); ISSUE1(1); ISSUE1(2);

    for (int kc = 0; kc < 128; kc++) {
        if (kc < 126) asm volatile("cp.async.wait_group 2;" ::: "memory");
        else          asm volatile("cp.async.wait_group 0;" ::: "memory");
        __syncthreads();
        if (kc < 125) ISSUE1(kc + 3);

        const uint32_t abase = sb + (kc & 3) * STG1;
        const uint32_t bbase = abase + B1_OFF;

#pragma unroll
        for (int ks = 0; ks < 2; ks++) {
            uint32_t af[2][2][4];
#pragma unroll
            for (int s = 0; s < 2; s++)
#pragma unroll
                for (int mi = 0; mi < 2; mi++) {
                    int row = warp_m * 32 + mi * 16 + (lane & 15);
                    int off = row * 128 + s * 64 + ks * 32 + (lane >> 4) * 16;
                    LDSM4(af[s][mi], abase + SWZ128(off));
                }
#pragma unroll
            for (int s = 0; s < 2; s++) {
                uint32_t bf[2][2];
                {
                    int row = warp_n * 16 + (lane & 7) + ((lane >> 4) & 1) * 8;
                    int off = row * 128 + s * 64 + ks * 32 + ((lane >> 3) & 1) * 16;
                    uint32_t q[4];
                    LDSM4(q, bbase + SWZ128(off));
                    bf[0][0] = q[0]; bf[0][1] = q[1];
                    bf[1][0] = q[2]; bf[1][1] = q[3];
                }
                if (s == 0) {
#pragma unroll
                    for (int mi = 0; mi < 2; mi++)
#pragma unroll
                        for (int nj = 0; nj < 2; nj++)
                            MMA16816(accm[mi * 2 + nj], af[0][mi], bf[nj]);
#pragma unroll
                    for (int mi = 0; mi < 2; mi++)
#pragma unroll
                        for (int nj = 0; nj < 2; nj++)
                            MMA16816(accc[mi * 2 + nj], af[1][mi], bf[nj]);
                } else {
#pragma unroll
                    for (int mi = 0; mi < 2; mi++)
#pragma unroll
                        for (int nj = 0; nj < 2; nj++)
                            MMA16816(accc[mi * 2 + nj], af[0][mi], bf[nj]);
                }
            }
        }
    }

    // epilogue: tanh + fp16 split, written straight from fragments
#pragma unroll
    for (int mi = 0; mi < 2; mi++)
#pragma unroll
        for (int nj = 0; nj < 2; nj++) {
            int t = mi * 2 + nj;
            int r0 = m0 + warp_m * 32 + mi * 16 + (lane >> 2);
            int c0 = n0 + warp_n * 16 + nj * 8 + (lane & 3) * 2;
            float ba = b1[c0], bb = b1[c0 + 1];
            float t0 = tanhf(accm[t][0] + fmaf(accc[t][0], LO_INVF, ba));
            float t1 = tanhf(accm[t][1] + fmaf(accc[t][1], LO_INVF, bb));
            float t2 = tanhf(accm[t][2] + fmaf(accc[t][2], LO_INVF, ba));
            float t3 = tanhf(accm[t][3] + fmaf(accc[t][3], LO_INVF, bb));
            __half h0 = __float2half_rn(t0), h1 = __float2half_rn(t1);
            __half h2 = __float2half_rn(t2), h3 = __float2half_rn(t3);
            __half l0 = __float2half_rn((t0 - __half2float(h0)) * LO_SCALE);
            __half l1 = __float2half_rn((t1 - __half2float(h1)) * LO_SCALE);
            __half l2 = __float2half_rn((t2 - __half2float(h2)) * LO_SCALE);
            __half l3 = __float2half_rn((t3 - __half2float(h3)) * LO_SCALE);
            size_t oa = ((size_t)r0 * HID + c0) >> 1;
            size_t ob = ((size_t)(r0 + 8) * HID + c0) >> 1;
            ((__half2*)g_Ah)[oa] = __halves2half2(h0, h1);
            ((__half2*)g_Ah)[ob] = __halves2half2(h2, h3);
            ((__half2*)g_Al)[oa] = __halves2half2(l0, l1);
            ((__half2*)g_Al)[ob] = __halves2half2(l2, l3);
        }
#undef ISSUE1
}

// SMEM (GEMM2): 4 stages x 28KB. Stage rows are 128B = [hi 64B | lo 64B].
#define STAGE   28672
#define B_SOFF  16384
#define SMEMSZ  (4 * STAGE)   // 114688
#define EPIT    98            // epilogue plane pitch (floats)

// ---------------- kernel: GEMM2 (mma.sync fp16-split) + spline ----------
__global__ __launch_bounds__(256, 2)
void k_gemm2(const float* __restrict__ b2, const float* __restrict__ x_in,
             const float* __restrict__ ps, float* __restrict__ out_phi) {
    extern __shared__ char sm2[];
    const uint32_t sb = (uint32_t)__cvta_generic_to_shared(sm2);
    const int tid  = threadIdx.x;
    const int wid  = tid >> 5;
    const int lane = tid & 31;
    const int warp_m = wid & 3;
    const int warp_n = wid >> 2;
    const int m0 = blockIdx.x * 128;
    const int n0 = blockIdx.y * 96;

    float accm[12][4], accc[12][4];
#pragma unroll
    for (int t = 0; t < 12; t++)
#pragma unroll
        for (int j = 0; j < 4; j++) { accm[t][j] = 0.f; accc[t][j] = 0.f; }

#define ISSUE(KC)                                                              \
    do {                                                                       \
        const int k0_ = (KC) * 32;                                             \
        const uint32_t st_ = sb + ((KC) & 3) * STAGE;                          \
        _Pragma("unroll")                                                      \
        for (int p_ = 0; p_ < 4; p_++) {          /* A: 1024 16B chunks */     \
            int c_ = tid + p_ * 256;                                           \
            int r_ = c_ >> 3, q_ = c_ & 7;                                     \
            const __half* src_ = ((q_ >> 2) ? g_Al : g_Ah) +                   \
                                 (size_t)(m0 + r_) * HID + k0_ + (q_ & 3) * 8; \
            uint32_t off_ = (uint32_t)(r_ * 128 + q_ * 16);                    \
            CP16(st_ + SWZ128(off_), src_);                                    \
        }                                                                      \
        _Pragma("unroll")                                                      \
        for (int p_ = 0; p_ < 3; p_++) {          /* B: 768 16B chunks */      \
            int c_ = tid + p_ * 256;                                           \
            int r_ = c_ >> 3, q_ = c_ & 7;                                     \
            const __half* src_ = ((q_ >> 2) ? g_Bl : g_Bh) +                   \
                                 (size_t)(n0 + r_) * HID + k0_ + (q_ & 3) * 8; \
            uint32_t off_ = (uint32_t)(r_ * 128 + q_ * 16);                    \
            CP16(st_ + B_SOFF + SWZ128(off_), src_);                           \
        }                                                                      \
        asm volatile("cp.async.commit_group;" ::: "memory");                   \
    } while (0)

    ISSUE(0); ISSUE(1); ISSUE(2);

    for (int kc = 0; kc < 16; kc++) {
        asm volatile("cp.async.wait_group 2;" ::: "memory");
        __syncthreads();
        if (kc < 13) ISSUE(kc + 3);

        const uint32_t abase = sb + (kc & 3) * STAGE;
        const uint32_t bbase = abase + B_SOFF;

#pragma unroll
        for (int ks = 0; ks < 2; ks++) {
            uint32_t af[2][2][4];
#pragma unroll
            for (int s = 0; s < 2; s++)
#pragma unroll
                for (int mi = 0; mi < 2; mi++) {
                    int row = warp_m * 32 + mi * 16 + (lane & 15);
                    int off = row * 128 + s * 64 + ks * 32 + (lane >> 4) * 16;
                    LDSM4(af[s][mi], abase + SWZ128(off));
                }
#pragma unroll
            for (int s = 0; s < 2; s++) {
                uint32_t bf[6][2];
#pragma unroll
                for (int j = 0; j < 3; j++) {
                    int row = warp_n * 48 + j * 16 + (lane & 7) + ((lane >> 4) & 1) * 8;
                    int off = row * 128 + s * 64 + ks * 32 + ((lane >> 3) & 1) * 16;
                    uint32_t q[4];
                    LDSM4(q, bbase + SWZ128(off));
                    bf[2 * j][0] = q[0]; bf[2 * j][1] = q[1];
                    bf[2 * j + 1][0] = q[2]; bf[2 * j + 1][1] = q[3];
                }
                if (s == 0) {
#pragma unroll
                    for (int mi = 0; mi < 2; mi++)
#pragma unroll
                        for (int nj = 0; nj < 6; nj++)
                            MMA16816(accm[mi * 6 + nj], af[0][mi], bf[nj]);
#pragma unroll
                    for (int mi = 0; mi < 2; mi++)
#pragma unroll
                        for (int nj = 0; nj < 6; nj++)
                            MMA16816(accc[mi * 6 + nj], af[1][mi], bf[nj]);
                } else {
#pragma unroll
                    for (int mi = 0; mi < 2; mi++)
#pragma unroll
                        for (int nj = 0; nj < 6; nj++)
                            MMA16816(accc[mi * 6 + nj], af[0][mi], bf[nj]);
                }
            }
        }
    }
    __syncthreads();

    // ---- epilogue: exchange fragments through SMEM, then spline ----
    float* mp = (float*)sm2;               // main plane [128][EPIT]
    float* cpl = (float*)sm2 + 128 * EPIT; // corr plane
#pragma unroll
    for (int mi = 0; mi < 2; mi++)
#pragma unroll
        for (int nj = 0; nj < 6; nj++) {
            int t = mi * 6 + nj;
            int row = warp_m * 32 + mi * 16 + (lane >> 2);
            int col = warp_n * 48 + nj * 8 + (lane & 3) * 2;
            *(float2*)&mp[row * EPIT + col]        = make_float2(accm[t][0], accm[t][1]);
            *(float2*)&mp[(row + 8) * EPIT + col]  = make_float2(accm[t][2], accm[t][3]);
            *(float2*)&cpl[row * EPIT + col]       = make_float2(accc[t][0], accc[t][1]);
            *(float2*)&cpl[(row + 8) * EPIT + col] = make_float2(accc[t][2], accc[t][3]);
        }
    __syncthreads();

    const float psv = ps[0];

#pragma unroll 1
    for (int it = 0; it < 2; it++) {
        int idx = tid + it * 256;          // 512 (b,s) pairs
        int m   = idx >> 2;                // 0..127
        int grp = idx & 3;                 // 0..3
        const int b = m0 + m;
        const int s_glob = blockIdx.y * 4 + grp;
        const int cb = s_glob * 24;
        const int base = m * EPIT + grp * 24;

        float v[16];
#pragma unroll
        for (int cc = 0; cc < 16; cc++) {
            float arg = mp[base + cc] + fmaf(cpl[base + cc], LO_INVF, b2[cb + cc]);
            v[cc] = ftanh(arg);
        }

        float hm = v[0], wm = v[8];
#pragma unroll
        for (int i = 1; i < KNOT; i++) {
            hm = fmaxf(hm, v[i]);
            wm = fmaxf(wm, v[8 + i]);
        }
        float he[KNOT], we[KNOT];
        float hs = 0.f, ws = 0.f;
#pragma unroll
        for (int i = 0; i < KNOT; i++) {
            he[i] = fexp(v[i] - hm);      hs += he[i];
            we[i] = fexp(v[8 + i] - wm);  ws += we[i];
        }
        float hscale = TWO_PI_F / hs;
        float wscale = TWO_PI_F / ws;
        float h[KNOT], w[KNOT];
#pragma unroll
        for (int i = 0; i < KNOT; i++) {
            h[i] = he[i] * hscale;
            w[i] = we[i] * wscale;
        }

        const float x = x_in[(size_t)b * S_OUTD + s_glob];

        int kc2 = 0;
        ff2 cw = {0.f, 0.f};
#pragma unroll
        for (int i = 0; i < KNOT; i++) {
            cw = ff_addf(cw, w[i]);
            kc2 += (((cw.hi - x) + cw.lo) < 0.f) ? 1 : 0;
        }
        int ki = kc2 < (KNOT - 1) ? kc2 : (KNOT - 1);
        int kn = (ki + 1) & (KNOT - 1);

        float w_k = 0.f, h_k = 0.f;
        ff2 x_km1 = {0.f, 0.f}, phi_km1 = {0.f, 0.f};
        ff2 pw = {0.f, 0.f}, ph = {0.f, 0.f};
#pragma unroll
        for (int i = 0; i < KNOT; i++) {
            if (i == ki) {
                w_k = w[i]; h_k = h[i];
                if (i == 0) { x_km1.hi = -EPS_F; x_km1.lo = 0.f; }
                else        { x_km1 = pw; }
                phi_km1 = ph;
            }
            pw = ff_addf(pw, w[i]);
            ph = ff_addf(ph, h[i]);
        }

        float dr0 = ftanh(mp[base + 16 + ki] +
                          fmaf(cpl[base + 16 + ki], LO_INVF, b2[cb + 16 + ki]));
        float dr1 = ftanh(mp[base + 16 + kn] +
                          fmaf(cpl[base + 16 + kn], LO_INVF, b2[cb + 16 + kn]));
        float d_k   = log1pf(fexp(dr0));
        float d_kp1 = log1pf(fexp(dr1));

        float s_k   = h_k / w_k;
        float alpha = ((x - x_km1.hi) - x_km1.lo) / w_k;
        float a1m   = alpha * (1.f - alpha);
        float denom = s_k + (d_kp1 + d_k - 2.f * s_k) * a1m;
        float frac  = h_k * fmaf(s_k * alpha, alpha, d_k * a1m) / denom;

        ff2 phif = ff_addf(phi_km1, frac);
        phif = ff_addf(phif, psv);
        float phiv = phif.hi + phif.lo;
        if (phiv >= TWO_PI_F) phiv -= TWO_PI_F;
        if (phiv >= TWO_PI_F) phiv -= TWO_PI_F;
        if (phiv < 0.f) phiv += TWO_PI_F;
        out_phi[(size_t)b * S_OUTD + s_glob] = phiv;

        float om   = 1.f - alpha;
        float grad = s_k * s_k *
                     fmaf(d_kp1 * alpha, alpha, fmaf(2.f * s_k, a1m, d_k * om * om)) /
                     (denom * denom);
        // deterministic 4-lane partial sum of log(grad) over this CTA's groups
        float lgv = logf(grad);
        lgv += __shfl_xor_sync(0xffffffffu, lgv, 1);
        lgv += __shfl_xor_sync(0xffffffffu, lgv, 2);
        if (grp == 0)
            g_part[(size_t)b * 1024 + blockIdx.y] = lgv;
    }
#undef ISSUE
}

// ---------------- kernel: deterministic log-density reduction ----------
__global__ void k_ldsum(const float* __restrict__ ld_in,
                        float* __restrict__ out_ld) {
    __shared__ double sh[256];
    int b = blockIdx.x;
    double sm = 0.0;
    for (int i = threadIdx.x; i < 1024; i += 256)
        sm += (double)g_part[(size_t)b * 1024 + i];
    sh[threadIdx.x] = sm;
    __syncthreads();
    for (int o = 128; o > 0; o >>= 1) {
        if (threadIdx.x < o) sh[threadIdx.x] += sh[threadIdx.x + o];
        __syncthreads();
    }
    if (threadIdx.x == 0) out_ld[b] = (float)((double)ld_in[b] - sh[0]);
}

// ---------------- launcher ----------------------------------------------
extern "C" void kernel_launch(void* const* d_in, const int* in_sizes, int n_in,
                              void* d_out, int out_size) {
    const float* x_in      = (const float*)d_in[0];
    const float* x_passive = (const float*)d_in[1];
    const float* ld_in     = (const float*)d_in[2];
    const float* w1        = (const float*)d_in[3];
    const float* b1        = (const float*)d_in[4];
    const float* w2        = (const float*)d_in[5];
    const float* b2        = (const float*)d_in[6];
    const float* ps        = (const float*)d_in[7];
    (void)in_sizes; (void)n_in; (void)out_size;

    float* out_phi = (float*)d_out;
    float* out_ld  = (float*)d_out + (size_t)B_DIM * S_OUTD;

    cudaFuncSetAttribute(k_gemm1m, cudaFuncAttributeMaxDynamicSharedMemorySize,
                         SM1SZ);
    cudaFuncSetAttribute(k_gemm2, cudaFuncAttributeMaxDynamicSharedMemorySize,
                         SMEMSZ);

    k_zero<<<1, 32>>>();
    k_fuse1<<<256 + WS_F1, 256>>>(x_passive, w2);
    k_finalize<<<1, 32>>>();
    k_fuse2<<<512 + 1024 + WS_F2, 256>>>(x_passive, w1, w2);
    k_gemm1m<<<128, 256, SM1SZ>>>(b1);
    k_gemm2<<<dim3(B_DIM / 128, NCOL / 96), 256, SMEMSZ>>>(b2, x_in, ps, out_phi);
    k_ldsum<<<B_DIM, 256>>>(ld_in, out_ld);
}

// round 16
// speedup vs baseline: 1.0530x; 1.0036x over previous
#include <cuda_runtime.h>
#include <cuda_fp16.h>
#include <cstdint>
#include <math.h>

// Problem constants
#define B_DIM   1024
#define S_IN    4096
#define S_OUTD  4096
#define KNOT    8
#define HID     512
#define NCOL    (S_OUTD * 3 * KNOT)    // 98304
#define NELEM   ((size_t)B_DIM * S_IN) // 4194304
#define TWO_PI_F 6.28318530717958647692f
#define EPS_F    1e-6f
#define LO_SCALE 2048.0f
#define LO_INVF  (1.0f / 2048.0f)

// wsplit partition: 24576 blocks total, split across fuse1/fuse2
#define WS_TOTAL 24576
#define WS_F1    12288
#define WS_F2    (WS_TOTAL - WS_F1)    // 12288

// ---------------- device scratch (static, no allocation) ----------------
static __device__ double g_ps[256];    // stats partial sums (per block)
static __device__ double g_ps2[256];
static __device__ float  g_mean;
static __device__ float  g_std;
static __device__ __align__(16) float g_part[(size_t)B_DIM * 1024];  // 4 MB
// fp16 2-way splits (lo pre-scaled by 2048)
static __device__ __align__(16) __half g_XNh[NELEM];                // xn
static __device__ __align__(16) __half g_XNl[NELEM];
static __device__ __align__(16) __half g_W1h[(size_t)HID * S_IN];   // w1^T
static __device__ __align__(16) __half g_W1l[(size_t)HID * S_IN];
static __device__ __align__(16) __half g_Ah[B_DIM * HID];           // H
static __device__ __align__(16) __half g_Al[B_DIM * HID];
static __device__ __align__(16) __half g_Bh[(size_t)NCOL * HID];    // w2^T
static __device__ __align__(16) __half g_Bl[(size_t)NCOL * HID];

// ---------------- FMA-pipe transcendentals (avoid MUFU) ------------------
static __device__ __forceinline__ float fexp(float x) {
    float t = x * 1.4426950408889634f;          // log2(e)
    float n = rintf(t);
    float f = fmaf(n, -0.693359375f, x);        // ln2 hi
    f = fmaf(n, 2.12194440e-4f, f);             // ln2 lo
    float p = 1.9841269841e-4f;
    p = fmaf(p, f, 1.3888888889e-3f);
    p = fmaf(p, f, 8.3333333333e-3f);
    p = fmaf(p, f, 4.1666666667e-2f);
    p = fmaf(p, f, 1.6666666667e-1f);
    p = fmaf(p, f, 0.5f);
    p = fmaf(p, f, 1.0f);
    p = fmaf(p, f, 1.0f);
    int j = (int)n;
    float s = __int_as_float((j + 127) << 23);
    return p * s;
}

static __device__ __forceinline__ float ftanh(float x) {
    float a = fminf(fabsf(x), 9.0f);
    float e = fexp(-2.0f * a);
    float d = 1.0f + e;
    float r;
    asm("rcp.approx.f32 %0, %1;" : "=f"(r) : "f"(d));
    r = r * (2.0f - d * r);
    float tt = (1.0f - e) * r;
    return copysignf(tt, x);
}

// ---------------- float-float (TwoSum) helpers ---------------------------
struct ff2 { float hi, lo; };
static __device__ __forceinline__ ff2 ff_renorm(float s, float e) {
    float t = s + e;
    return {t, e - (t - s)};
}
static __device__ __forceinline__ ff2 ff_addf(ff2 a, float b) {
    float s  = a.hi + b;
    float bb = s - a.hi;
    float err = (a.hi - (s - bb)) + (b - bb);
    return ff_renorm(s, err + a.lo);
}

// ---------------- wsplit body (shared by the fused kernels) -------------
static __device__ __forceinline__ void wsplit_body(const float* __restrict__ w2,
                                                   int wb, float* scratch) {
    const int n0 = (wb % 3072) * 32;
    const int k0 = (wb / 3072) * 64;
    const int tid = threadIdx.x;
#pragma unroll
    for (int p = 0; p < 8; p++) {
        int idx = tid + p * 256;
        int kr = idx >> 5, nc = idx & 31;
        scratch[kr * 33 + nc] = w2[(size_t)(k0 + kr) * NCOL + n0 + nc];
    }
    __syncthreads();
#pragma unroll
    for (int p = 0; p < 4; p++) {
        int idx = tid + p * 256;
        int n = idx >> 5, kp = idx & 31;
        float v0 = scratch[(2 * kp) * 33 + n];
        float v1 = scratch[(2 * kp + 1) * 33 + n];
        __half h0 = __float2half_rn(v0);
        __half h1 = __float2half_rn(v1);
        __half l0 = __float2half_rn((v0 - __half2float(h0)) * LO_SCALE);
        __half l1 = __float2half_rn((v1 - __half2float(h1)) * LO_SCALE);
        size_t o = ((size_t)(n0 + n) * HID + k0 + 2 * kp) >> 1;
        ((__half2*)g_Bh)[o] = __halves2half2(h0, h1);
        ((__half2*)g_Bl)[o] = __halves2half2(l0, l1);
    }
}

// ---------------- k_finalize: reduce stats partials ----------------------
__global__ void k_finalize() {
    __shared__ double sh[256];
    __shared__ double sh2[256];
    int t = threadIdx.x;
    sh[t] = g_ps[t]; sh2[t] = g_ps2[t];
    __syncthreads();
    for (int o = 128; o > 0; o >>= 1) {
        if (t < o) { sh[t] += sh[t + o]; sh2[t] += sh2[t + o]; }
        __syncthreads();
    }
    if (t == 0) {
        double n = (double)NELEM;
        double mean = sh[0] / n;
        double var  = (sh2[0] - sh[0] * sh[0] / n) / (n - 1.0);
        g_mean = (float)mean;
        g_std  = (float)sqrt(var);
    }
}

// ---- fuse1: stats (256) || w1split (1024) || wsplit[0, WS_F1) -----------
// w1split is independent of the stats finalize, so it runs pre-finalize.
__global__ void k_fuse1(const float* __restrict__ xp,
                        const float* __restrict__ w1,
                        const float* __restrict__ w2) {
    __shared__ float scratch[64 * 33];
    const int bx = blockIdx.x;
    if (bx < 256) {
        double s = 0.0, s2 = 0.0;
        for (size_t i = (size_t)bx * blockDim.x + threadIdx.x; i < NELEM;
             i += (size_t)256 * blockDim.x) {
            float v = xp[i];
            s  += (double)v;
            s2 += (double)v * (double)v;
        }
        double* sh  = (double*)scratch;          // 256 doubles
        double* sh2 = (double*)scratch + 256;    // 256 doubles (4KB total)
        sh[threadIdx.x] = s; sh2[threadIdx.x] = s2;
        __syncthreads();
        for (int o = 128; o > 0; o >>= 1) {
            if (threadIdx.x < o) {
                sh[threadIdx.x]  += sh[threadIdx.x + o];
                sh2[threadIdx.x] += sh2[threadIdx.x + o];
            }
            __syncthreads();
        }
        if (threadIdx.x == 0) {
            g_ps[bx]  = sh[0];
            g_ps2[bx] = sh2[0];
        }
    } else if (bx < 256 + 1024) {
        // w1 transpose + split: wb in [0,1024): n0=(wb&15)*32, k0=(wb>>4)*64
        const int wb = bx - 256;
        const int n0 = (wb & 15) * 32, k0 = (wb >> 4) * 64;
        const int tid = threadIdx.x;
#pragma unroll
        for (int p = 0; p < 8; p++) {
            int idx = tid + p * 256;
            int kr = idx >> 5, nc = idx & 31;
            scratch[kr * 33 + nc] = w1[(size_t)(k0 + kr) * HID + n0 + nc];
        }
        __syncthreads();
#pragma unroll
        for (int p = 0; p < 4; p++) {
            int idx = tid + p * 256;
            int n = idx >> 5, kp = idx & 31;
            float v0 = scratch[(2 * kp) * 33 + n];
            float v1 = scratch[(2 * kp + 1) * 33 + n];
            __half h0 = __float2half_rn(v0);
            __half h1 = __float2half_rn(v1);
            __half l0 = __float2half_rn((v0 - __half2float(h0)) * LO_SCALE);
            __half l1 = __float2half_rn((v1 - __half2float(h1)) * LO_SCALE);
            size_t o = ((size_t)(n0 + n) * S_IN + k0 + 2 * kp) >> 1;
            ((__half2*)g_W1h)[o] = __halves2half2(h0, h1);
            ((__half2*)g_W1l)[o] = __halves2half2(l0, l1);
        }
    } else {
        wsplit_body(w2, bx - 1280, scratch);
    }
}

// ---------------- fuse2: xnsplit (512) || wsplit[WS_F1, end) -------------
__global__ void k_fuse2(const float* __restrict__ xp,
                        const float* __restrict__ w2) {
    __shared__ float scratch[64 * 33];
    const int bx = blockIdx.x;
    if (bx < 512) {
        float mean = g_mean;
        float inv  = 1.0f / g_std;
        const float4* src = (const float4*)xp;
        for (size_t i = (size_t)bx * blockDim.x + threadIdx.x;
             i < NELEM / 4; i += (size_t)512 * blockDim.x) {
            float4 v = src[i];
            v.x = (v.x - mean) * inv; v.y = (v.y - mean) * inv;
            v.z = (v.z - mean) * inv; v.w = (v.w - mean) * inv;
            __half h0 = __float2half_rn(v.x), h1 = __float2half_rn(v.y);
            __half h2 = __float2half_rn(v.z), h3 = __float2half_rn(v.w);
            __half l0 = __float2half_rn((v.x - __half2float(h0)) * LO_SCALE);
            __half l1 = __float2half_rn((v.y - __half2float(h1)) * LO_SCALE);
            __half l2 = __float2half_rn((v.z - __half2float(h2)) * LO_SCALE);
            __half l3 = __float2half_rn((v.w - __half2float(h3)) * LO_SCALE);
            __half2 hv[2] = {__halves2half2(h0, h1), __halves2half2(h2, h3)};
            __half2 lv[2] = {__halves2half2(l0, l1), __halves2half2(l2, l3)};
            ((uint2*)g_XNh)[i] = *(uint2*)hv;
            ((uint2*)g_XNl)[i] = *(uint2*)lv;
        }
    } else {
        wsplit_body(w2, (bx - 512) + WS_F1, scratch);
    }
}

// ---------------- mma.sync helpers ---------------------------------------
#define SWZ128(x) ((x) ^ (((x) >> 3) & 0x70))

#define LDSM4(r, addr)                                                        \
    asm volatile("ldmatrix.sync.aligned.m8n8.x4.shared.b16 {%0,%1,%2,%3}, [%4];" \
                 : "=r"((r)[0]), "=r"((r)[1]), "=r"((r)[2]), "=r"((r)[3])     \
                 : "r"(addr))

#define MMA16816(d, a, b)                                                     \
    asm volatile("mma.sync.aligned.m16n8k16.row.col.f32.f16.f16.f32 "         \
                 "{%0,%1,%2,%3},{%4,%5,%6,%7},{%8,%9},{%0,%1,%2,%3};"         \
                 : "+f"((d)[0]), "+f"((d)[1]), "+f"((d)[2]), "+f"((d)[3])     \
                 : "r"((a)[0]), "r"((a)[1]), "r"((a)[2]), "r"((a)[3]),        \
                   "r"((b)[0]), "r"((b)[1]))

#define CP16(dst, src)                                                        \
    asm volatile("cp.async.cg.shared.global [%0], [%1], 16;" :: "r"(dst), "l"(src))

// ---------------- k_gemm1m: GEMM1 (128 blocks, 64x64 tile), uncontended -
// CTA: M=64 x N=64, K=4096 in 128 chunks of 32, 4 stages, occ 2.
// 8 warps as 2(m) x 4(n): warp tile 32 x 16.
#define STG1    16384
#define B1_OFF  8192
#define SM1SZ   (4 * STG1)   // 65536

__global__ __launch_bounds__(256, 2)
void k_gemm1m(const float* __restrict__ b1) {
    extern __shared__ char sm1[];
    const int bxf = blockIdx.x;
    const uint32_t sb = (uint32_t)__cvta_generic_to_shared(sm1);
    const int tid  = threadIdx.x;
    const int wid  = tid >> 5;
    const int lane = tid & 31;
    const int warp_m = wid & 1;
    const int warp_n = wid >> 1;
    const int m0 = (bxf & 15) * 64;
    const int n0 = (bxf >> 4) * 64;

    float accm[4][4], accc[4][4];
#pragma unroll
    for (int t = 0; t < 4; t++)
#pragma unroll
        for (int j = 0; j < 4; j++) { accm[t][j] = 0.f; accc[t][j] = 0.f; }

#define ISSUE1(KC)                                                             \
    do {                                                                       \
        const int k0_ = (KC) * 32;                                             \
        const uint32_t st_ = sb + ((KC) & 3) * STG1;                           \
        _Pragma("unroll")                                                      \
        for (int p_ = 0; p_ < 2; p_++) {          /* A: 512 16B chunks */      \
            int c_ = tid + p_ * 256;                                           \
            int r_ = c_ >> 3, q_ = c_ & 7;                                     \
            const __half* src_ = ((q_ >> 2) ? g_XNl : g_XNh) +                 \
                                 (size_t)(m0 + r_) * S_IN + k0_ + (q_ & 3) * 8;\
            CP16(st_ + SWZ128((uint32_t)(r_ * 128 + q_ * 16)), src_);          \
        }                                                                      \
        _Pragma("unroll")                                                      \
        for (int p_ = 0; p_ < 2; p_++) {          /* B: 512 16B chunks */      \
            int c_ = tid + p_ * 256;                                           \
            int r_ = c_ >> 3, q_ = c_ & 7;                                     \
            const __half* src_ = ((q_ >> 2) ? g_W1l : g_W1h) +                 \
                                 (size_t)(n0 + r_) * S_IN + k0_ + (q_ & 3) * 8;\
            CP16(st_ + B1_OFF + SWZ128((uint32_t)(r_ * 128 + q_ * 16)), src_); \
        }                                                                      \
        asm volatile("cp.async.commit_group;" ::: "memory");                   \
    } while (0)

    ISSUE1(0); ISSUE1(1); ISSUE1(2);

    for (int kc = 0; kc < 128; kc++) {
        if (kc < 126) asm volatile("cp.async.wait_group 2;" ::: "memory");
        else          asm volatile("cp.async.wait_group 0;" ::: "memory");
        __syncthreads();
        if (kc < 125) ISSUE1(kc + 3);

        const uint32_t abase = sb + (kc & 3) * STG1;
        const uint32_t bbase = abase + B1_OFF;

#pragma unroll
        for (int ks = 0; ks < 2; ks++) {
            uint32_t af[2][2][4];
#pragma unroll
            for (int s = 0; s < 2; s++)
#pragma unroll
                for (int mi = 0; mi < 2; mi++) {
                    int row = warp_m * 32 + mi * 16 + (lane & 15);
                    int off = row * 128 + s * 64 + ks * 32 + (lane >> 4) * 16;
                    LDSM4(af[s][mi], abase + SWZ128(off));
                }
#pragma unroll
            for (int s = 0; s < 2; s++) {
                uint32_t bf[2][2];
                {
                    int row = warp_n * 16 + (lane & 7) + ((lane >> 4) & 1) * 8;
                    int off = row * 128 + s * 64 + ks * 32 + ((lane >> 3) & 1) * 16;
                    uint32_t q[4];
                    LDSM4(q, bbase + SWZ128(off));
                    bf[0][0] = q[0]; bf[0][1] = q[1];
                    bf[1][0] = q[2]; bf[1][1] = q[3];
                }
                if (s == 0) {
#pragma unroll
                    for (int mi = 0; mi < 2; mi++)
#pragma unroll
                        for (int nj = 0; nj < 2; nj++)
                            MMA16816(accm[mi * 2 + nj], af[0][mi], bf[nj]);
#pragma unroll
                    for (int mi = 0; mi < 2; mi++)
#pragma unroll
                        for (int nj = 0; nj < 2; nj++)
                            MMA16816(accc[mi * 2 + nj], af[1][mi], bf[nj]);
                } else {
#pragma unroll
                    for (int mi = 0; mi < 2; mi++)
#pragma unroll
                        for (int nj = 0; nj < 2; nj++)
                            MMA16816(accc[mi * 2 + nj], af[0][mi], bf[nj]);
                }
            }
        }
    }

    // epilogue: tanh + fp16 split, written straight from fragments
#pragma unroll
    for (int mi = 0; mi < 2; mi++)
#pragma unroll
        for (int nj = 0; nj < 2; nj++) {
            int t = mi * 2 + nj;
            int r0 = m0 + warp_m * 32 + mi * 16 + (lane >> 2);
            int c0 = n0 + warp_n * 16 + nj * 8 + (lane & 3) * 2;
            float ba = b1[c0], bb = b1[c0 + 1];
            float t0 = tanhf(accm[t][0] + fmaf(accc[t][0], LO_INVF, ba));
            float t1 = tanhf(accm[t][1] + fmaf(accc[t][1], LO_INVF, bb));
            float t2 = tanhf(accm[t][2] + fmaf(accc[t][2], LO_INVF, ba));
            float t3 = tanhf(accm[t][3] + fmaf(accc[t][3], LO_INVF, bb));
            __half h0 = __float2half_rn(t0), h1 = __float2half_rn(t1);
            __half h2 = __float2half_rn(t2), h3 = __float2half_rn(t3);
            __half l0 = __float2half_rn((t0 - __half2float(h0)) * LO_SCALE);
            __half l1 = __float2half_rn((t1 - __half2float(h1)) * LO_SCALE);
            __half l2 = __float2half_rn((t2 - __half2float(h2)) * LO_SCALE);
            __half l3 = __float2half_rn((t3 - __half2float(h3)) * LO_SCALE);
            size_t oa = ((size_t)r0 * HID + c0) >> 1;
            size_t ob = ((size_t)(r0 + 8) * HID + c0) >> 1;
            ((__half2*)g_Ah)[oa] = __halves2half2(h0, h1);
            ((__half2*)g_Ah)[ob] = __halves2half2(h2, h3);
            ((__half2*)g_Al)[oa] = __halves2half2(l0, l1);
            ((__half2*)g_Al)[ob] = __halves2half2(l2, l3);
        }
#undef ISSUE1
}

// SMEM (GEMM2): 4 stages x 28KB. Stage rows are 128B = [hi 64B | lo 64B].
#define STAGE   28672
#define B_SOFF  16384
#define SMEMSZ  (4 * STAGE)   // 114688
#define EPIT    98            // epilogue plane pitch (floats)

// ---------------- kernel: GEMM2 (mma.sync fp16-split) + spline ----------
__global__ __launch_bounds__(256, 2)
void k_gemm2(const float* __restrict__ b2, const float* __restrict__ x_in,
             const float* __restrict__ ps, float* __restrict__ out_phi) {
    extern __shared__ char sm2[];
    const uint32_t sb = (uint32_t)__cvta_generic_to_shared(sm2);
    const int tid  = threadIdx.x;
    const int wid  = tid >> 5;
    const int lane = tid & 31;
    const int warp_m = wid & 3;
    const int warp_n = wid >> 2;
    const int m0 = blockIdx.x * 128;
    const int n0 = blockIdx.y * 96;

    float accm[12][4], accc[12][4];
#pragma unroll
    for (int t = 0; t < 12; t++)
#pragma unroll
        for (int j = 0; j < 4; j++) { accm[t][j] = 0.f; accc[t][j] = 0.f; }

#define ISSUE(KC)                                                              \
    do {                                                                       \
        const int k0_ = (KC) * 32;                                             \
        const uint32_t st_ = sb + ((KC) & 3) * STAGE;                          \
        _Pragma("unroll")                                                      \
        for (int p_ = 0; p_ < 4; p_++) {          /* A: 1024 16B chunks */     \
            int c_ = tid + p_ * 256;                                           \
            int r_ = c_ >> 3, q_ = c_ & 7;                                     \
            const __half* src_ = ((q_ >> 2) ? g_Al : g_Ah) +                   \
                                 (size_t)(m0 + r_) * HID + k0_ + (q_ & 3) * 8; \
            uint32_t off_ = (uint32_t)(r_ * 128 + q_ * 16);                    \
            CP16(st_ + SWZ128(off_), src_);                                    \
        }                                                                      \
        _Pragma("unroll")                                                      \
        for (int p_ = 0; p_ < 3; p_++) {          /* B: 768 16B chunks */      \
            int c_ = tid + p_ * 256;                                           \
            int r_ = c_ >> 3, q_ = c_ & 7;                                     \
            const __half* src_ = ((q_ >> 2) ? g_Bl : g_Bh) +                   \
                                 (size_t)(n0 + r_) * HID + k0_ + (q_ & 3) * 8; \
            uint32_t off_ = (uint32_t)(r_ * 128 + q_ * 16);                    \
            CP16(st_ + B_SOFF + SWZ128(off_), src_);                           \
        }                                                                      \
        asm volatile("cp.async.commit_group;" ::: "memory");                   \
    } while (0)

    ISSUE(0); ISSUE(1); ISSUE(2);

    for (int kc = 0; kc < 16; kc++) {
        asm volatile("cp.async.wait_group 2;" ::: "memory");
        __syncthreads();
        if (kc < 13) ISSUE(kc + 3);

        const uint32_t abase = sb + (kc & 3) * STAGE;
        const uint32_t bbase = abase + B_SOFF;

#pragma unroll
        for (int ks = 0; ks < 2; ks++) {
            uint32_t af[2][2][4];
#pragma unroll
            for (int s = 0; s < 2; s++)
#pragma unroll
                for (int mi = 0; mi < 2; mi++) {
                    int row = warp_m * 32 + mi * 16 + (lane & 15);
                    int off = row * 128 + s * 64 + ks * 32 + (lane >> 4) * 16;
                    LDSM4(af[s][mi], abase + SWZ128(off));
                }
#pragma unroll
            for (int s = 0; s < 2; s++) {
                uint32_t bf[6][2];
#pragma unroll
                for (int j = 0; j < 3; j++) {
                    int row = warp_n * 48 + j * 16 + (lane & 7) + ((lane >> 4) & 1) * 8;
                    int off = row * 128 + s * 64 + ks * 32 + ((lane >> 3) & 1) * 16;
                    uint32_t q[4];
                    LDSM4(q, bbase + SWZ128(off));
                    bf[2 * j][0] = q[0]; bf[2 * j][1] = q[1];
                    bf[2 * j + 1][0] = q[2]; bf[2 * j + 1][1] = q[3];
                }
                if (s == 0) {
#pragma unroll
                    for (int mi = 0; mi < 2; mi++)
#pragma unroll
                        for (int nj = 0; nj < 6; nj++)
                            MMA16816(accm[mi * 6 + nj], af[0][mi], bf[nj]);
#pragma unroll
                    for (int mi = 0; mi < 2; mi++)
#pragma unroll
                        for (int nj = 0; nj < 6; nj++)
                            MMA16816(accc[mi * 6 + nj], af[1][mi], bf[nj]);
                } else {
#pragma unroll
                    for (int mi = 0; mi < 2; mi++)
#pragma unroll
                        for (int nj = 0; nj < 6; nj++)
                            MMA16816(accc[mi * 6 + nj], af[0][mi], bf[nj]);
                }
            }
        }
    }
    __syncthreads();

    // ---- epilogue: exchange fragments through SMEM, then spline ----
    float* mp = (float*)sm2;               // main plane [128][EPIT]
    float* cpl = (float*)sm2 + 128 * EPIT; // corr plane
#pragma unroll
    for (int mi = 0; mi < 2; mi++)
#pragma unroll
        for (int nj = 0; nj < 6; nj++) {
            int t = mi * 6 + nj;
            int row = warp_m * 32 + mi * 16 + (lane >> 2);
            int col = warp_n * 48 + nj * 8 + (lane & 3) * 2;
            *(float2*)&mp[row * EPIT + col]        = make_float2(accm[t][0], accm[t][1]);
            *(float2*)&mp[(row + 8) * EPIT + col]  = make_float2(accm[t][2], accm[t][3]);
            *(float2*)&cpl[row * EPIT + col]       = make_float2(accc[t][0], accc[t][1]);
            *(float2*)&cpl[(row + 8) * EPIT + col] = make_float2(accc[t][2], accc[t][3]);
        }
    __syncthreads();

    const float psv = ps[0];

#pragma unroll 1
    for (int it = 0; it < 2; it++) {
        int idx = tid + it * 256;          // 512 (b,s) pairs
        int m   = idx >> 2;                // 0..127
        int grp = idx & 3;                 // 0..3
        const int b = m0 + m;
        const int s_glob = blockIdx.y * 4 + grp;
        const int cb = s_glob * 24;
        const int base = m * EPIT + grp * 24;

        float v[16];
#pragma unroll
        for (int cc = 0; cc < 16; cc++) {
            float arg = mp[base + cc] + fmaf(cpl[base + cc], LO_INVF, b2[cb + cc]);
            v[cc] = ftanh(arg);
        }

        float hm = v[0], wm = v[8];
#pragma unroll
        for (int i = 1; i < KNOT; i++) {
            hm = fmaxf(hm, v[i]);
            wm = fmaxf(wm, v[8 + i]);
        }
        float he[KNOT], we[KNOT];
        float hs = 0.f, ws = 0.f;
#pragma unroll
        for (int i = 0; i < KNOT; i++) {
            he[i] = fexp(v[i] - hm);      hs += he[i];
            we[i] = fexp(v[8 + i] - wm);  ws += we[i];
        }
        float hscale = TWO_PI_F / hs;
        float wscale = TWO_PI_F / ws;
        float h[KNOT], w[KNOT];
#pragma unroll
        for (int i = 0; i < KNOT; i++) {
            h[i] = he[i] * hscale;
            w[i] = we[i] * wscale;
        }

        const float x = x_in[(size_t)b * S_OUTD + s_glob];

        int kc2 = 0;
        ff2 cw = {0.f, 0.f};
#pragma unroll
        for (int i = 0; i < KNOT; i++) {
            cw = ff_addf(cw, w[i]);
            kc2 += (((cw.hi - x) + cw.lo) < 0.f) ? 1 : 0;
        }
        int ki = kc2 < (KNOT - 1) ? kc2 : (KNOT - 1);
        int kn = (ki + 1) & (KNOT - 1);

        float w_k = 0.f, h_k = 0.f;
        ff2 x_km1 = {0.f, 0.f}, phi_km1 = {0.f, 0.f};
        ff2 pw = {0.f, 0.f}, ph = {0.f, 0.f};
#pragma unroll
        for (int i = 0; i < KNOT; i++) {
            if (i == ki) {
                w_k = w[i]; h_k = h[i];
                if (i == 0) { x_km1.hi = -EPS_F; x_km1.lo = 0.f; }
                else        { x_km1 = pw; }
                phi_km1 = ph;
            }
            pw = ff_addf(pw, w[i]);
            ph = ff_addf(ph, h[i]);
        }

        float dr0 = ftanh(mp[base + 16 + ki] +
                          fmaf(cpl[base + 16 + ki], LO_INVF, b2[cb + 16 + ki]));
        float dr1 = ftanh(mp[base + 16 + kn] +
                          fmaf(cpl[base + 16 + kn], LO_INVF, b2[cb + 16 + kn]));
        float d_k   = log1pf(fexp(dr0));
        float d_kp1 = log1pf(fexp(dr1));

        float s_k   = h_k / w_k;
        float alpha = ((x - x_km1.hi) - x_km1.lo) / w_k;
        float a1m   = alpha * (1.f - alpha);
        float denom = s_k + (d_kp1 + d_k - 2.f * s_k) * a1m;
        float frac  = h_k * fmaf(s_k * alpha, alpha, d_k * a1m) / denom;

        ff2 phif = ff_addf(phi_km1, frac);
        phif = ff_addf(phif, psv);
        float phiv = phif.hi + phif.lo;
        if (phiv >= TWO_PI_F) phiv -= TWO_PI_F;
        if (phiv >= TWO_PI_F) phiv -= TWO_PI_F;
        if (phiv < 0.f) phiv += TWO_PI_F;
        out_phi[(size_t)b * S_OUTD + s_glob] = phiv;

        float om   = 1.f - alpha;
        float grad = s_k * s_k *
                     fmaf(d_kp1 * alpha, alpha, fmaf(2.f * s_k, a1m, d_k * om * om)) /
                     (denom * denom);
        // deterministic 4-lane partial sum of log(grad) over this CTA's groups
        float lgv = logf(grad);
        lgv += __shfl_xor_sync(0xffffffffu, lgv, 1);
        lgv += __shfl_xor_sync(0xffffffffu, lgv, 2);
        if (grp == 0)
            g_part[(size_t)b * 1024 + blockIdx.y] = lgv;
    }
#undef ISSUE
}

// ---------------- kernel: deterministic log-density reduction ----------
__global__ void k_ldsum(const float* __restrict__ ld_in,
                        float* __restrict__ out_ld) {
    __shared__ double sh[256];
    int b = blockIdx.x;
    double sm = 0.0;
    for (int i = threadIdx.x; i < 1024; i += 256)
        sm += (double)g_part[(size_t)b * 1024 + i];
    sh[threadIdx.x] = sm;
    __syncthreads();
    for (int o = 128; o > 0; o >>= 1) {
        if (threadIdx.x < o) sh[threadIdx.x] += sh[threadIdx.x + o];
        __syncthreads();
    }
    if (threadIdx.x == 0) out_ld[b] = (float)((double)ld_in[b] - sh[0]);
}

// ---------------- launcher ----------------------------------------------
extern "C" void kernel_launch(void* const* d_in, const int* in_sizes, int n_in,
                              void* d_out, int out_size) {
    const float* x_in      = (const float*)d_in[0];
    const float* x_passive = (const float*)d_in[1];
    const float* ld_in     = (const float*)d_in[2];
    const float* w1        = (const float*)d_in[3];
    const float* b1        = (const float*)d_in[4];
    const float* w2        = (const float*)d_in[5];
    const float* b2        = (const float*)d_in[6];
    const float* ps        = (const float*)d_in[7];
    (void)in_sizes; (void)n_in; (void)out_size;

    float* out_phi = (float*)d_out;
    float* out_ld  = (float*)d_out + (size_t)B_DIM * S_OUTD;

    cudaFuncSetAttribute(k_gemm1m, cudaFuncAttributeMaxDynamicSharedMemorySize,
                         SM1SZ);
    cudaFuncSetAttribute(k_gemm2, cudaFuncAttributeMaxDynamicSharedMemorySize,
                         SMEMSZ);

    k_fuse1<<<256 + 1024 + WS_F1, 256>>>(x_passive, w1, w2);
    k_finalize<<<1, 256>>>();
    k_fuse2<<<512 + WS_F2, 256>>>(x_passive, w2);
    k_gemm1m<<<128, 256, SM1SZ>>>(b1);
    k_gemm2<<<dim3(B_DIM / 128, NCOL / 96), 256, SMEMSZ>>>(b2, x_in, ps, out_phi);
    k_ldsum<<<B_DIM, 256>>>(ld_in, out_ld);
}

// round 17
// speedup vs baseline: 1.0571x; 1.0039x over previous
#include <cuda_runtime.h>
#include <cuda_fp16.h>
#include <cstdint>
#include <math.h>

// Problem constants
#define B_DIM   1024
#define S_IN    4096
#define S_OUTD  4096
#define KNOT    8
#define HID     512
#define NCOL    (S_OUTD * 3 * KNOT)    // 98304
#define NELEM   ((size_t)B_DIM * S_IN) // 4194304
#define TWO_PI_F 6.28318530717958647692f
#define EPS_F    1e-6f
#define LO_SCALE 2048.0f
#define LO_INVF  (1.0f / 2048.0f)

// wsplit partition: 24576 blocks total, split across fuse1/fuse2
#define WS_TOTAL 24576
#define WS_F1    12288
#define WS_F2    (WS_TOTAL - WS_F1)    // 12288

// ---------------- device scratch (static, no allocation) ----------------
static __device__ double g_ps[256];    // stats partial sums (per block)
static __device__ double g_ps2[256];
static __device__ float  g_mean;
static __device__ float  g_std;
static __device__ __align__(16) float g_part[(size_t)B_DIM * 1024];  // 4 MB
// fp16 2-way splits (lo pre-scaled by 2048)
static __device__ __align__(16) __half g_XNh[NELEM];                // xn
static __device__ __align__(16) __half g_XNl[NELEM];
static __device__ __align__(16) __half g_W1h[(size_t)HID * S_IN];   // w1^T
static __device__ __align__(16) __half g_W1l[(size_t)HID * S_IN];
static __device__ __align__(16) __half g_Ah[B_DIM * HID];           // H
static __device__ __align__(16) __half g_Al[B_DIM * HID];
static __device__ __align__(16) __half g_Bh[(size_t)NCOL * HID];    // w2^T
static __device__ __align__(16) __half g_Bl[(size_t)NCOL * HID];

// ---------------- FMA-pipe transcendentals (avoid MUFU) ------------------
static __device__ __forceinline__ float fexp(float x) {
    float t = x * 1.4426950408889634f;          // log2(e)
    float n = rintf(t);
    float f = fmaf(n, -0.693359375f, x);        // ln2 hi
    f = fmaf(n, 2.12194440e-4f, f);             // ln2 lo
    float p = 1.9841269841e-4f;
    p = fmaf(p, f, 1.3888888889e-3f);
    p = fmaf(p, f, 8.3333333333e-3f);
    p = fmaf(p, f, 4.1666666667e-2f);
    p = fmaf(p, f, 1.6666666667e-1f);
    p = fmaf(p, f, 0.5f);
    p = fmaf(p, f, 1.0f);
    p = fmaf(p, f, 1.0f);
    int j = (int)n;
    float s = __int_as_float((j + 127) << 23);
    return p * s;
}

static __device__ __forceinline__ float ftanh(float x) {
    float a = fminf(fabsf(x), 9.0f);
    float e = fexp(-2.0f * a);
    float d = 1.0f + e;
    float r;
    asm("rcp.approx.f32 %0, %1;" : "=f"(r) : "f"(d));
    r = r * (2.0f - d * r);
    float tt = (1.0f - e) * r;
    return copysignf(tt, x);
}

// ---------------- float-float (TwoSum) helpers ---------------------------
struct ff2 { float hi, lo; };
static __device__ __forceinline__ ff2 ff_renorm(float s, float e) {
    float t = s + e;
    return {t, e - (t - s)};
}
static __device__ __forceinline__ ff2 ff_addf(ff2 a, float b) {
    float s  = a.hi + b;
    float bb = s - a.hi;
    float err = (a.hi - (s - bb)) + (b - bb);
    return ff_renorm(s, err + a.lo);
}

// ---------------- wsplit body (shared by the fused kernels) -------------
static __device__ __forceinline__ void wsplit_body(const float* __restrict__ w2,
                                                   int wb, float* scratch) {
    const int n0 = (wb % 3072) * 32;
    const int k0 = (wb / 3072) * 64;
    const int tid = threadIdx.x;
#pragma unroll
    for (int p = 0; p < 8; p++) {
        int idx = tid + p * 256;
        int kr = idx >> 5, nc = idx & 31;
        scratch[kr * 33 + nc] = w2[(size_t)(k0 + kr) * NCOL + n0 + nc];
    }
    __syncthreads();
#pragma unroll
    for (int p = 0; p < 4; p++) {
        int idx = tid + p * 256;
        int n = idx >> 5, kp = idx & 31;
        float v0 = scratch[(2 * kp) * 33 + n];
        float v1 = scratch[(2 * kp + 1) * 33 + n];
        __half h0 = __float2half_rn(v0);
        __half h1 = __float2half_rn(v1);
        __half l0 = __float2half_rn((v0 - __half2float(h0)) * LO_SCALE);
        __half l1 = __float2half_rn((v1 - __half2float(h1)) * LO_SCALE);
        size_t o = ((size_t)(n0 + n) * HID + k0 + 2 * kp) >> 1;
        ((__half2*)g_Bh)[o] = __halves2half2(h0, h1);
        ((__half2*)g_Bl)[o] = __halves2half2(l0, l1);
    }
}

// ---------------- k_finalize: reduce stats partials ----------------------
__global__ void k_finalize() {
    __shared__ double sh[256];
    __shared__ double sh2[256];
    int t = threadIdx.x;
    sh[t] = g_ps[t]; sh2[t] = g_ps2[t];
    __syncthreads();
    for (int o = 128; o > 0; o >>= 1) {
        if (t < o) { sh[t] += sh[t + o]; sh2[t] += sh2[t + o]; }
        __syncthreads();
    }
    if (t == 0) {
        double n = (double)NELEM;
        double mean = sh[0] / n;
        double var  = (sh2[0] - sh[0] * sh[0] / n) / (n - 1.0);
        g_mean = (float)mean;
        g_std  = (float)sqrt(var);
    }
}

// ---- fuse1: stats (256) || w1split (1024) || wsplit[0, WS_F1) -----------
__global__ void k_fuse1(const float* __restrict__ xp,
                        const float* __restrict__ w1,
                        const float* __restrict__ w2) {
    __shared__ float scratch[64 * 33];
    const int bx = blockIdx.x;
    if (bx < 256) {
        double s = 0.0, s2 = 0.0;
        for (size_t i = (size_t)bx * blockDim.x + threadIdx.x; i < NELEM;
             i += (size_t)256 * blockDim.x) {
            float v = xp[i];
            s  += (double)v;
            s2 += (double)v * (double)v;
        }
        double* sh  = (double*)scratch;
        double* sh2 = (double*)scratch + 256;
        sh[threadIdx.x] = s; sh2[threadIdx.x] = s2;
        __syncthreads();
        for (int o = 128; o > 0; o >>= 1) {
            if (threadIdx.x < o) {
                sh[threadIdx.x]  += sh[threadIdx.x + o];
                sh2[threadIdx.x] += sh2[threadIdx.x + o];
            }
            __syncthreads();
        }
        if (threadIdx.x == 0) {
            g_ps[bx]  = sh[0];
            g_ps2[bx] = sh2[0];
        }
    } else if (bx < 256 + 1024) {
        const int wb = bx - 256;
        const int n0 = (wb & 15) * 32, k0 = (wb >> 4) * 64;
        const int tid = threadIdx.x;
#pragma unroll
        for (int p = 0; p < 8; p++) {
            int idx = tid + p * 256;
            int kr = idx >> 5, nc = idx & 31;
            scratch[kr * 33 + nc] = w1[(size_t)(k0 + kr) * HID + n0 + nc];
        }
        __syncthreads();
#pragma unroll
        for (int p = 0; p < 4; p++) {
            int idx = tid + p * 256;
            int n = idx >> 5, kp = idx & 31;
            float v0 = scratch[(2 * kp) * 33 + n];
            float v1 = scratch[(2 * kp + 1) * 33 + n];
            __half h0 = __float2half_rn(v0);
            __half h1 = __float2half_rn(v1);
            __half l0 = __float2half_rn((v0 - __half2float(h0)) * LO_SCALE);
            __half l1 = __float2half_rn((v1 - __half2float(h1)) * LO_SCALE);
            size_t o = ((size_t)(n0 + n) * S_IN + k0 + 2 * kp) >> 1;
            ((__half2*)g_W1h)[o] = __halves2half2(h0, h1);
            ((__half2*)g_W1l)[o] = __halves2half2(l0, l1);
        }
    } else {
        wsplit_body(w2, bx - 1280, scratch);
    }
}

// ---------------- fuse2: xnsplit (512) || wsplit[WS_F1, end) -------------
__global__ void k_fuse2(const float* __restrict__ xp,
                        const float* __restrict__ w2) {
    __shared__ float scratch[64 * 33];
    const int bx = blockIdx.x;
    if (bx < 512) {
        float mean = g_mean;
        float inv  = 1.0f / g_std;
        const float4* src = (const float4*)xp;
        for (size_t i = (size_t)bx * blockDim.x + threadIdx.x;
             i < NELEM / 4; i += (size_t)512 * blockDim.x) {
            float4 v = src[i];
            v.x = (v.x - mean) * inv; v.y = (v.y - mean) * inv;
            v.z = (v.z - mean) * inv; v.w = (v.w - mean) * inv;
            __half h0 = __float2half_rn(v.x), h1 = __float2half_rn(v.y);
            __half h2 = __float2half_rn(v.z), h3 = __float2half_rn(v.w);
            __half l0 = __float2half_rn((v.x - __half2float(h0)) * LO_SCALE);
            __half l1 = __float2half_rn((v.y - __half2float(h1)) * LO_SCALE);
            __half l2 = __float2half_rn((v.z - __half2float(h2)) * LO_SCALE);
            __half l3 = __float2half_rn((v.w - __half2float(h3)) * LO_SCALE);
            __half2 hv[2] = {__halves2half2(h0, h1), __halves2half2(h2, h3)};
            __half2 lv[2] = {__halves2half2(l0, l1), __halves2half2(l2, l3)};
            ((uint2*)g_XNh)[i] = *(uint2*)hv;
            ((uint2*)g_XNl)[i] = *(uint2*)lv;
        }
    } else {
        wsplit_body(w2, (bx - 512) + WS_F1, scratch);
    }
}

// ---------------- mma.sync helpers ---------------------------------------
#define SWZ128(x) ((x) ^ (((x) >> 3) & 0x70))

#define LDSM4(r, addr)                                                        \
    asm volatile("ldmatrix.sync.aligned.m8n8.x4.shared.b16 {%0,%1,%2,%3}, [%4];" \
                 : "=r"((r)[0]), "=r"((r)[1]), "=r"((r)[2]), "=r"((r)[3])     \
                 : "r"(addr))

#define MMA16816(d, a, b)                                                     \
    asm volatile("mma.sync.aligned.m16n8k16.row.col.f32.f16.f16.f32 "         \
                 "{%0,%1,%2,%3},{%4,%5,%6,%7},{%8,%9},{%0,%1,%2,%3};"         \
                 : "+f"((d)[0]), "+f"((d)[1]), "+f"((d)[2]), "+f"((d)[3])     \
                 : "r"((a)[0]), "r"((a)[1]), "r"((a)[2]), "r"((a)[3]),        \
                   "r"((b)[0]), "r"((b)[1]))

#define CP16(dst, src)                                                        \
    asm volatile("cp.async.cg.shared.global [%0], [%1], 16;" :: "r"(dst), "l"(src))

// ---------------- k_gemm1m: GEMM1 (256 blocks, 64x32 tile) --------------
// CTA: M=64 x N=32, K=4096 in 128 chunks of 32, 4 stages, occ 2.
// 8 warps as 4(m) x 2(n): warp tile 16 x 16.
#define STG1    12288
#define B1_OFF  8192
#define SM1SZ   (4 * STG1)   // 49152

__global__ __launch_bounds__(256, 2)
void k_gemm1m(const float* __restrict__ b1) {
    extern __shared__ char sm1[];
    const int bxf = blockIdx.x;
    const uint32_t sb = (uint32_t)__cvta_generic_to_shared(sm1);
    const int tid  = threadIdx.x;
    const int wid  = tid >> 5;
    const int lane = tid & 31;
    const int warp_m = wid & 3;        // 16 rows each
    const int warp_n = wid >> 2;       // 16 cols each
    const int m0 = (bxf & 15) * 64;
    const int n0 = (bxf >> 4) * 32;

    float accm[2][4], accc[2][4];
#pragma unroll
    for (int t = 0; t < 2; t++)
#pragma unroll
        for (int j = 0; j < 4; j++) { accm[t][j] = 0.f; accc[t][j] = 0.f; }

#define ISSUE1(KC)                                                             \
    do {                                                                       \
        const int k0_ = (KC) * 32;                                             \
        const uint32_t st_ = sb + ((KC) & 3) * STG1;                           \
        _Pragma("unroll")                                                      \
        for (int p_ = 0; p_ < 2; p_++) {          /* A: 512 16B chunks */      \
            int c_ = tid + p_ * 256;                                           \
            int r_ = c_ >> 3, q_ = c_ & 7;                                     \
            const __half* src_ = ((q_ >> 2) ? g_XNl : g_XNh) +                 \
                                 (size_t)(m0 + r_) * S_IN + k0_ + (q_ & 3) * 8;\
            CP16(st_ + SWZ128((uint32_t)(r_ * 128 + q_ * 16)), src_);          \
        }                                                                      \
        {                                         /* B: 256 16B chunks */      \
            int c_ = tid;                                                      \
            int r_ = c_ >> 3, q_ = c_ & 7;                                     \
            const __half* src_ = ((q_ >> 2) ? g_W1l : g_W1h) +                 \
                                 (size_t)(n0 + r_) * S_IN + k0_ + (q_ & 3) * 8;\
            CP16(st_ + B1_OFF + SWZ128((uint32_t)(r_ * 128 + q_ * 16)), src_); \
        }                                                                      \
        asm volatile("cp.async.commit_group;" ::: "memory");                   \
    } while (0)

    ISSUE1(0); ISSUE1(1); ISSUE1(2);

    for (int kc = 0; kc < 128; kc++) {
        if (kc < 126) asm volatile("cp.async.wait_group 2;" ::: "memory");
        else          asm volatile("cp.async.wait_group 0;" ::: "memory");
        __syncthreads();
        if (kc < 125) ISSUE1(kc + 3);

        const uint32_t abase = sb + (kc & 3) * STG1;
        const uint32_t bbase = abase + B1_OFF;

#pragma unroll
        for (int ks = 0; ks < 2; ks++) {
            uint32_t af[2][4];   // [split], m16 x k16
#pragma unroll
            for (int s = 0; s < 2; s++) {
                int row = warp_m * 16 + (lane & 15);
                int off = row * 128 + s * 64 + ks * 32 + (lane >> 4) * 16;
                LDSM4(af[s], abase + SWZ128(off));
            }
#pragma unroll
            for (int s = 0; s < 2; s++) {
                uint32_t bf[2][2];
                {
                    int row = warp_n * 16 + (lane & 7) + ((lane >> 4) & 1) * 8;
                    int off = row * 128 + s * 64 + ks * 32 + ((lane >> 3) & 1) * 16;
                    uint32_t q[4];
                    LDSM4(q, bbase + SWZ128(off));
                    bf[0][0] = q[0]; bf[0][1] = q[1];
                    bf[1][0] = q[2]; bf[1][1] = q[3];
                }
                if (s == 0) {
#pragma unroll
                    for (int nj = 0; nj < 2; nj++)
                        MMA16816(accm[nj], af[0], bf[nj]);
#pragma unroll
                    for (int nj = 0; nj < 2; nj++)
                        MMA16816(accc[nj], af[1], bf[nj]);
                } else {
#pragma unroll
                    for (int nj = 0; nj < 2; nj++)
                        MMA16816(accc[nj], af[0], bf[nj]);
                }
            }
        }
    }

    // epilogue: tanh + fp16 split, written straight from fragments
#pragma unroll
    for (int nj = 0; nj < 2; nj++) {
        int t = nj;
        int r0 = m0 + warp_m * 16 + (lane >> 2);
        int c0 = n0 + warp_n * 16 + nj * 8 + (lane & 3) * 2;
        float ba = b1[c0], bb = b1[c0 + 1];
        float t0 = tanhf(accm[t][0] + fmaf(accc[t][0], LO_INVF, ba));
        float t1 = tanhf(accm[t][1] + fmaf(accc[t][1], LO_INVF, bb));
        float t2 = tanhf(accm[t][2] + fmaf(accc[t][2], LO_INVF, ba));
        float t3 = tanhf(accm[t][3] + fmaf(accc[t][3], LO_INVF, bb));
        __half h0 = __float2half_rn(t0), h1 = __float2half_rn(t1);
        __half h2 = __float2half_rn(t2), h3 = __float2half_rn(t3);
        __half l0 = __float2half_rn((t0 - __half2float(h0)) * LO_SCALE);
        __half l1 = __float2half_rn((t1 - __half2float(h1)) * LO_SCALE);
        __half l2 = __float2half_rn((t2 - __half2float(h2)) * LO_SCALE);
        __half l3 = __float2half_rn((t3 - __half2float(h3)) * LO_SCALE);
        size_t oa = ((size_t)r0 * HID + c0) >> 1;
        size_t ob = ((size_t)(r0 + 8) * HID + c0) >> 1;
        ((__half2*)g_Ah)[oa] = __halves2half2(h0, h1);
        ((__half2*)g_Ah)[ob] = __halves2half2(h2, h3);
        ((__half2*)g_Al)[oa] = __halves2half2(l0, l1);
        ((__half2*)g_Al)[ob] = __halves2half2(l2, l3);
    }
#undef ISSUE1
}

// SMEM (GEMM2): 4 stages x 28KB. Stage rows are 128B = [hi 64B | lo 64B].
#define STAGE   28672
#define B_SOFF  16384
#define SMEMSZ  (4 * STAGE)   // 114688
#define EPIT    98            // epilogue plane pitch (floats)

// ---------------- kernel: GEMM2 (mma.sync fp16-split) + spline ----------
__global__ __launch_bounds__(256, 2)
void k_gemm2(const float* __restrict__ b2, const float* __restrict__ x_in,
             const float* __restrict__ ps, float* __restrict__ out_phi) {
    extern __shared__ char sm2[];
    const uint32_t sb = (uint32_t)__cvta_generic_to_shared(sm2);
    const int tid  = threadIdx.x;
    const int wid  = tid >> 5;
    const int lane = tid & 31;
    const int warp_m = wid & 3;
    const int warp_n = wid >> 2;
    const int m0 = blockIdx.x * 128;
    const int n0 = blockIdx.y * 96;

    float accm[12][4], accc[12][4];
#pragma unroll
    for (int t = 0; t < 12; t++)
#pragma unroll
        for (int j = 0; j < 4; j++) { accm[t][j] = 0.f; accc[t][j] = 0.f; }

#define ISSUE(KC)                                                              \
    do {                                                                       \
        const int k0_ = (KC) * 32;                                             \
        const uint32_t st_ = sb + ((KC) & 3) * STAGE;                          \
        _Pragma("unroll")                                                      \
        for (int p_ = 0; p_ < 4; p_++) {          /* A: 1024 16B chunks */     \
            int c_ = tid + p_ * 256;                                           \
            int r_ = c_ >> 3, q_ = c_ & 7;                                     \
            const __half* src_ = ((q_ >> 2) ? g_Al : g_Ah) +                   \
                                 (size_t)(m0 + r_) * HID + k0_ + (q_ & 3) * 8; \
            uint32_t off_ = (uint32_t)(r_ * 128 + q_ * 16);                    \
            CP16(st_ + SWZ128(off_), src_);                                    \
        }                                                                      \
        _Pragma("unroll")                                                      \
        for (int p_ = 0; p_ < 3; p_++) {          /* B: 768 16B chunks */      \
            int c_ = tid + p_ * 256;                                           \
            int r_ = c_ >> 3, q_ = c_ & 7;                                     \
            const __half* src_ = ((q_ >> 2) ? g_Bl : g_Bh) +                   \
                                 (size_t)(n0 + r_) * HID + k0_ + (q_ & 3) * 8; \
            uint32_t off_ = (uint32_t)(r_ * 128 + q_ * 16);                    \
            CP16(st_ + B_SOFF + SWZ128(off_), src_);                           \
        }                                                                      \
        asm volatile("cp.async.commit_group;" ::: "memory");                   \
    } while (0)

    ISSUE(0); ISSUE(1); ISSUE(2);

    for (int kc = 0; kc < 16; kc++) {
        asm volatile("cp.async.wait_group 2;" ::: "memory");
        __syncthreads();
        if (kc < 13) ISSUE(kc + 3);

        const uint32_t abase = sb + (kc & 3) * STAGE;
        const uint32_t bbase = abase + B_SOFF;

#pragma unroll
        for (int ks = 0; ks < 2; ks++) {
            uint32_t af[2][2][4];
#pragma unroll
            for (int s = 0; s < 2; s++)
#pragma unroll
                for (int mi = 0; mi < 2; mi++) {
                    int row = warp_m * 32 + mi * 16 + (lane & 15);
                    int off = row * 128 + s * 64 + ks * 32 + (lane >> 4) * 16;
                    LDSM4(af[s][mi], abase + SWZ128(off));
                }
#pragma unroll
            for (int s = 0; s < 2; s++) {
                uint32_t bf[6][2];
#pragma unroll
                for (int j = 0; j < 3; j++) {
                    int row = warp_n * 48 + j * 16 + (lane & 7) + ((lane >> 4) & 1) * 8;
                    int off = row * 128 + s * 64 + ks * 32 + ((lane >> 3) & 1) * 16;
                    uint32_t q[4];
                    LDSM4(q, bbase + SWZ128(off));
                    bf[2 * j][0] = q[0]; bf[2 * j][1] = q[1];
                    bf[2 * j + 1][0] = q[2]; bf[2 * j + 1][1] = q[3];
                }
                if (s == 0) {
#pragma unroll
                    for (int mi = 0; mi < 2; mi++)
#pragma unroll
                        for (int nj = 0; nj < 6; nj++)
                            MMA16816(accm[mi * 6 + nj], af[0][mi], bf[nj]);
#pragma unroll
                    for (int mi = 0; mi < 2; mi++)
#pragma unroll
                        for (int nj = 0; nj < 6; nj++)
                            MMA16816(accc[mi * 6 + nj], af[1][mi], bf[nj]);
                } else {
#pragma unroll
                    for (int mi = 0; mi < 2; mi++)
#pragma unroll
                        for (int nj = 0; nj < 6; nj++)
                            MMA16816(accc[mi * 6 + nj], af[0][mi], bf[nj]);
                }
            }
        }
    }
    __syncthreads();

    // ---- epilogue: exchange fragments through SMEM, then spline ----
    float* mp = (float*)sm2;               // main plane [128][EPIT]
    float* cpl = (float*)sm2 + 128 * EPIT; // corr plane
#pragma unroll
    for (int mi = 0; mi < 2; mi++)
#pragma unroll
        for (int nj = 0; nj < 6; nj++) {
            int t = mi * 6 + nj;
            int row = warp_m * 32 + mi * 16 + (lane >> 2);
            int col = warp_n * 48 + nj * 8 + (lane & 3) * 2;
            *(float2*)&mp[row * EPIT + col]        = make_float2(accm[t][0], accm[t][1]);
            *(float2*)&mp[(row + 8) * EPIT + col]  = make_float2(accm[t][2], accm[t][3]);
            *(float2*)&cpl[row * EPIT + col]       = make_float2(accc[t][0], accc[t][1]);
            *(float2*)&cpl[(row + 8) * EPIT + col] = make_float2(accc[t][2], accc[t][3]);
        }
    __syncthreads();

    const float psv = ps[0];

#pragma unroll 1
    for (int it = 0; it < 2; it++) {
        int idx = tid + it * 256;          // 512 (b,s) pairs
        int m   = idx >> 2;                // 0..127
        int grp = idx & 3;                 // 0..3
        const int b = m0 + m;
        const int s_glob = blockIdx.y * 4 + grp;
        const int cb = s_glob * 24;
        const int base = m * EPIT + grp * 24;

        float v[16];
#pragma unroll
        for (int cc = 0; cc < 16; cc++) {
            float arg = mp[base + cc] + fmaf(cpl[base + cc], LO_INVF, b2[cb + cc]);
            v[cc] = ftanh(arg);
        }

        float hm = v[0], wm = v[8];
#pragma unroll
        for (int i = 1; i < KNOT; i++) {
            hm = fmaxf(hm, v[i]);
            wm = fmaxf(wm, v[8 + i]);
        }
        float he[KNOT], we[KNOT];
        float hs = 0.f, ws = 0.f;
#pragma unroll
        for (int i = 0; i < KNOT; i++) {
            he[i] = fexp(v[i] - hm);      hs += he[i];
            we[i] = fexp(v[8 + i] - wm);  ws += we[i];
        }
        float hscale = TWO_PI_F / hs;
        float wscale = TWO_PI_F / ws;
        float h[KNOT], w[KNOT];
#pragma unroll
        for (int i = 0; i < KNOT; i++) {
            h[i] = he[i] * hscale;
            w[i] = we[i] * wscale;
        }

        const float x = x_in[(size_t)b * S_OUTD + s_glob];

        int kc2 = 0;
        ff2 cw = {0.f, 0.f};
#pragma unroll
        for (int i = 0; i < KNOT; i++) {
            cw = ff_addf(cw, w[i]);
            kc2 += (((cw.hi - x) + cw.lo) < 0.f) ? 1 : 0;
        }
        int ki = kc2 < (KNOT - 1) ? kc2 : (KNOT - 1);
        int kn = (ki + 1) & (KNOT - 1);

        float w_k = 0.f, h_k = 0.f;
        ff2 x_km1 = {0.f, 0.f}, phi_km1 = {0.f, 0.f};
        ff2 pw = {0.f, 0.f}, ph = {0.f, 0.f};
#pragma unroll
        for (int i = 0; i < KNOT; i++) {
            if (i == ki) {
                w_k = w[i]; h_k = h[i];
                if (i == 0) { x_km1.hi = -EPS_F; x_km1.lo = 0.f; }
                else        { x_km1 = pw; }
                phi_km1 = ph;
            }
            pw = ff_addf(pw, w[i]);
            ph = ff_addf(ph, h[i]);
        }

        float dr0 = ftanh(mp[base + 16 + ki] +
                          fmaf(cpl[base + 16 + ki], LO_INVF, b2[cb + 16 + ki]));
        float dr1 = ftanh(mp[base + 16 + kn] +
                          fmaf(cpl[base + 16 + kn], LO_INVF, b2[cb + 16 + kn]));
        float d_k   = log1pf(fexp(dr0));
        float d_kp1 = log1pf(fexp(dr1));

        float s_k   = h_k / w_k;
        float alpha = ((x - x_km1.hi) - x_km1.lo) / w_k;
        float a1m   = alpha * (1.f - alpha);
        float denom = s_k + (d_kp1 + d_k - 2.f * s_k) * a1m;
        float frac  = h_k * fmaf(s_k * alpha, alpha, d_k * a1m) / denom;

        ff2 phif = ff_addf(phi_km1, frac);
        phif = ff_addf(phif, psv);
        float phiv = phif.hi + phif.lo;
        if (phiv >= TWO_PI_F) phiv -= TWO_PI_F;
        if (phiv >= TWO_PI_F) phiv -= TWO_PI_F;
        if (phiv < 0.f) phiv += TWO_PI_F;
        out_phi[(size_t)b * S_OUTD + s_glob] = phiv;

        float om   = 1.f - alpha;
        float grad = s_k * s_k *
                     fmaf(d_kp1 * alpha, alpha, fmaf(2.f * s_k, a1m, d_k * om * om)) /
                     (denom * denom);
        // deterministic 4-lane partial sum of log(grad) over this CTA's groups
        float lgv = logf(grad);
        lgv += __shfl_xor_sync(0xffffffffu, lgv, 1);
        lgv += __shfl_xor_sync(0xffffffffu, lgv, 2);
        if (grp == 0)
            g_part[(size_t)b * 1024 + blockIdx.y] = lgv;
    }
#undef ISSUE
}

// ---------------- kernel: deterministic log-density reduction ----------
__global__ void k_ldsum(const float* __restrict__ ld_in,
                        float* __restrict__ out_ld) {
    __shared__ double sh[256];
    int b = blockIdx.x;
    double sm = 0.0;
    for (int i = threadIdx.x; i < 1024; i += 256)
        sm += (double)g_part[(size_t)b * 1024 + i];
    sh[threadIdx.x] = sm;
    __syncthreads();
    for (int o = 128; o > 0; o >>= 1) {
        if (threadIdx.x < o) sh[threadIdx.x] += sh[threadIdx.x + o];
        __syncthreads();
    }
    if (threadIdx.x == 0) out_ld[b] = (float)((double)ld_in[b] - sh[0]);
}

// ---------------- launcher ----------------------------------------------
extern "C" void kernel_launch(void* const* d_in, const int* in_sizes, int n_in,
                              void* d_out, int out_size) {
    const float* x_in      = (const float*)d_in[0];
    const float* x_passive = (const float*)d_in[1];
    const float* ld_in     = (const float*)d_in[2];
    const float* w1        = (const float*)d_in[3];
    const float* b1        = (const float*)d_in[4];
    const float* w2        = (const float*)d_in[5];
    const float* b2        = (const float*)d_in[6];
    const float* ps        = (const float*)d_in[7];
    (void)in_sizes; (void)n_in; (void)out_size;

    float* out_phi = (float*)d_out;
    float* out_ld  = (float*)d_out + (size_t)B_DIM * S_OUTD;

    cudaFuncSetAttribute(k_gemm1m, cudaFuncAttributeMaxDynamicSharedMemorySize,
                         SM1SZ);
    cudaFuncSetAttribute(k_gemm2, cudaFuncAttributeMaxDynamicSharedMemorySize,
                         SMEMSZ);

    k_fuse1<<<256 + 1024 + WS_F1, 256>>>(x_passive, w1, w2);
    k_finalize<<<1, 256>>>();
    k_fuse2<<<512 + WS_F2, 256>>>(x_passive, w2);
    k_gemm1m<<<256, 256, SM1SZ>>>(b1);
    k_gemm2<<<dim3(B_DIM / 128, NCOL / 96), 256, SMEMSZ>>>(b2, x_in, ps, out_phi);
    k_ldsum<<<B_DIM, 256>>>(ld_in, out_ld);
}